// round 3
// baseline (speedup 1.0000x reference)
#include <cuda_runtime.h>
#include <math.h>
#include <stdint.h>

// ---------------------------------------------------------------------------
// InterImageTokenizer: ViT patch-embed + cosine codebook assignment +
// per-row compaction + segment means + attention mask.
//
// Fixed shapes: B=64, C=3, HW=384, P=16 -> N=576 patches, D=Hd=768, V=1000.
// Outputs concatenated into d_out as fp32:
//   [0]  out    : [B, 577, 768]   = 28,360,704
//   [1]  labels : [B, 576] (cast) =     36,864
//   [2]  attn   : [B,1,577,577]   = 21,307,456
// ---------------------------------------------------------------------------

constexpr int CB   = 64;            // batch
constexpr int CC   = 3;
constexpr int CHW  = 384;
constexpr int CP   = 16;
constexpr int CG   = CHW / CP;      // 24
constexpr int CN   = CG * CG;       // 576
constexpr int CD   = CC * CP * CP;  // 768
constexpr int CHD  = 768;
constexpr int CV   = 1000;
constexpr int CBN  = CB * CN;       // 36864
constexpr int CNP1 = CN + 1;        // 577

// -------------------- device scratch (no allocations allowed) --------------
__device__ float g_patches[(size_t)CBN * CD];
__device__ float g_emb[(size_t)CBN * CHD];
__device__ float g_scores[(size_t)CBN * CV];
__device__ float g_Wt[CD * CHD];          // conv_w transposed: [d][h]
__device__ float g_vnT[CD * CV];          // normalized vocab transposed: [d][v]
__device__ float g_pnorm[CBN];
__device__ float g_maxdot[CBN];
__device__ int   g_amax[CBN];
__device__ int   g_labels0[CBN];
__device__ int   g_perm[CB * CN];
__device__ int   g_segstart[CB * CNP1];
__device__ int   g_nseg[CB];

// -------------------- prep: normalize vocab, write transposed --------------
__global__ void prep_vocab_kernel(const float* __restrict__ vocab) {
    int v = blockIdx.x;
    __shared__ float red[256];
    float s = 0.f;
    for (int d = threadIdx.x; d < CD; d += 256) {
        float x = vocab[(size_t)v * CD + d];
        s += x * x;
    }
    red[threadIdx.x] = s; __syncthreads();
    for (int o = 128; o > 0; o >>= 1) {
        if (threadIdx.x < o) red[threadIdx.x] += red[threadIdx.x + o];
        __syncthreads();
    }
    float invn = 1.0f / sqrtf(red[0]);
    for (int d = threadIdx.x; d < CD; d += 256)
        g_vnT[(size_t)d * CV + v] = vocab[(size_t)v * CD + d] * invn;
}

// -------------------- prep: transpose conv weight ---------------------------
__global__ void transpose_w_kernel(const float* __restrict__ W) {
    __shared__ float t[32][33];
    int x = blockIdx.x * 32 + threadIdx.x;  // d
    int y = blockIdx.y * 32 + threadIdx.y;  // h
    t[threadIdx.y][threadIdx.x] = W[(size_t)y * CD + x];
    __syncthreads();
    int xo = blockIdx.y * 32 + threadIdx.x; // h
    int yo = blockIdx.x * 32 + threadIdx.y; // d
    g_Wt[(size_t)yo * CHD + xo] = t[threadIdx.x][threadIdx.y];
}

// -------------------- patch extraction --------------------------------------
__global__ void extract_kernel(const float* __restrict__ px) {
    size_t idx = (size_t)blockIdx.x * blockDim.x + threadIdx.x;
    size_t total = (size_t)CBN * CD;
    if (idx >= total) return;
    int d = (int)(idx % CD);
    int n = (int)((idx / CD) % CN);
    int b = (int)(idx / ((size_t)CD * CN));
    int c  = d / (CP * CP);
    int r  = d % (CP * CP);
    int ph = r / CP, pw = r % CP;
    int hp = n / CG, wp = n % CG;
    g_patches[idx] = px[(((size_t)b * CC + c) * CHW + hp * CP + ph) * CHW + wp * CP + pw];
}

// -------------------- patch L2 norm ------------------------------------------
__global__ void pnorm_kernel() {
    int r = blockIdx.x;
    __shared__ float red[256];
    const float* p = &g_patches[(size_t)r * CD];
    float s = 0.f;
    for (int d = threadIdx.x; d < CD; d += 256) { float x = p[d]; s += x * x; }
    red[threadIdx.x] = s; __syncthreads();
    for (int o = 128; o > 0; o >>= 1) {
        if (threadIdx.x < o) red[threadIdx.x] += red[threadIdx.x + o];
        __syncthreads();
    }
    if (threadIdx.x == 0) g_pnorm[r] = sqrtf(red[0]);
}

// -------------------- tiled fp32 GEMM ----------------------------------------
// C[M,N] = A[M,K] * B[K,N] (+ bias[n] + pos[(m%576)+1][n] when epi==1)
#define SG_BM 128
#define SG_BN 128
#define SG_BK 8
__global__ void __launch_bounds__(256)
sgemm_kernel(const float* __restrict__ A, const float* __restrict__ Bm,
             float* __restrict__ C, int M, int Ncols, int K,
             const float* __restrict__ bias, const float* __restrict__ pos, int epi) {
    __shared__ float As[SG_BK][SG_BM];
    __shared__ float Bs[SG_BK][SG_BN];
    int tid = threadIdx.x;
    int tx = tid & 15, ty = tid >> 4;
    int rowBase = blockIdx.y * SG_BM;
    int colBase = blockIdx.x * SG_BN;

    int a_row = tid >> 1;                 // 0..127
    int a_k4  = (tid & 1) * 4;            // 0 or 4
    int b_row = tid >> 5;                 // 0..7
    int b_col4 = (tid & 31) * 4;          // 0..124

    float acc[8][8];
#pragma unroll
    for (int i = 0; i < 8; i++)
#pragma unroll
        for (int j = 0; j < 8; j++) acc[i][j] = 0.f;

    for (int k0 = 0; k0 < K; k0 += SG_BK) {
        float4 av = *reinterpret_cast<const float4*>(
            &A[(size_t)(rowBase + a_row) * K + k0 + a_k4]);
        As[a_k4 + 0][a_row] = av.x;
        As[a_k4 + 1][a_row] = av.y;
        As[a_k4 + 2][a_row] = av.z;
        As[a_k4 + 3][a_row] = av.w;

        int gcol = colBase + b_col4;
        float4 bv;
        if (gcol + 3 < Ncols) {
            bv = *reinterpret_cast<const float4*>(
                &Bm[(size_t)(k0 + b_row) * Ncols + gcol]);
        } else {
            float t0 = (gcol + 0 < Ncols) ? Bm[(size_t)(k0 + b_row) * Ncols + gcol + 0] : 0.f;
            float t1 = (gcol + 1 < Ncols) ? Bm[(size_t)(k0 + b_row) * Ncols + gcol + 1] : 0.f;
            float t2 = (gcol + 2 < Ncols) ? Bm[(size_t)(k0 + b_row) * Ncols + gcol + 2] : 0.f;
            float t3 = (gcol + 3 < Ncols) ? Bm[(size_t)(k0 + b_row) * Ncols + gcol + 3] : 0.f;
            bv = make_float4(t0, t1, t2, t3);
        }
        *reinterpret_cast<float4*>(&Bs[b_row][b_col4]) = bv;
        __syncthreads();

#pragma unroll
        for (int kk = 0; kk < SG_BK; kk++) {
            float ar[8], br[8];
#pragma unroll
            for (int i = 0; i < 8; i++) ar[i] = As[kk][ty * 8 + i];
#pragma unroll
            for (int j = 0; j < 8; j++) br[j] = Bs[kk][tx * 8 + j];
#pragma unroll
            for (int i = 0; i < 8; i++)
#pragma unroll
                for (int j = 0; j < 8; j++) acc[i][j] += ar[i] * br[j];
        }
        __syncthreads();
    }

#pragma unroll
    for (int i = 0; i < 8; i++) {
        int row = rowBase + ty * 8 + i;
        int prow = (row % CN) + 1;
#pragma unroll
        for (int j = 0; j < 8; j++) {
            int col = colBase + tx * 8 + j;
            if (col < Ncols) {
                float v = acc[i][j];
                if (epi) v += bias[col] + pos[(size_t)prow * CHD + col];
                C[(size_t)row * Ncols + col] = v;
            }
        }
    }
}

// -------------------- per-patch max/argmax over vocab ------------------------
__global__ void rowmax_kernel() {
    int r = blockIdx.x;
    const float* s = &g_scores[(size_t)r * CV];
    float best = -1e30f; int bi = 0x7fffffff;
    for (int v = threadIdx.x; v < CV; v += 256) {
        float x = s[v];
        if (x > best || (x == best && v < bi)) { best = x; bi = v; }
    }
    __shared__ float sv[256];
    __shared__ int   si[256];
    sv[threadIdx.x] = best; si[threadIdx.x] = bi; __syncthreads();
    for (int o = 128; o > 0; o >>= 1) {
        if (threadIdx.x < o) {
            float x2 = sv[threadIdx.x + o]; int i2 = si[threadIdx.x + o];
            if (x2 > sv[threadIdx.x] || (x2 == sv[threadIdx.x] && i2 < si[threadIdx.x])) {
                sv[threadIdx.x] = x2; si[threadIdx.x] = i2;
            }
        }
        __syncthreads();
    }
    if (threadIdx.x == 0) { g_maxdot[r] = sv[0]; g_amax[r] = si[0]; }
}

// -------------------- mask + global exclusive scan -> raw labels -------------
__global__ void label_scan_kernel() {
    __shared__ int sc[1024];
    int tid = threadIdx.x;
    int running = 0;
    for (int base = 0; base < CBN; base += 1024) {
        int i = base + tid;
        int m = 0, lab = 0;
        if (i < CBN) {
            float smin = 1.0f - g_maxdot[i] / g_pnorm[i];
            m = (smin > 0.1f) ? 1 : 0;
            lab = g_amax[i];
        }
        sc[tid] = m; __syncthreads();
        for (int off = 1; off < 1024; off <<= 1) {
            int v = (tid >= off) ? sc[tid - off] : 0;
            __syncthreads();
            sc[tid] += v;
            __syncthreads();
        }
        if (i < CBN) {
            int excl = sc[tid] - m;
            g_labels0[i] = m ? (CV + running + excl) : lab;
        }
        running += sc[1023];
        __syncthreads();
    }
}

// -------------------- per-row bitonic sort + unique-consecutive --------------
// labels fit in 16 bits (max V+B*N-1 = 37863) -> key = (label<<16)|n
__global__ void __launch_bounds__(1024)
compact_kernel(float* __restrict__ labels_out) {
    __shared__ unsigned int key[1024];
    __shared__ int sc[1024];
    int b = blockIdx.x, tid = threadIdx.x;
    key[tid] = (tid < CN) ? ((((unsigned)g_labels0[b * CN + tid]) << 16) | (unsigned)tid)
                          : 0xFFFFFFFFu;
    __syncthreads();

    for (int k = 2; k <= 1024; k <<= 1) {
        for (int j = k >> 1; j > 0; j >>= 1) {
            int ixj = tid ^ j;
            if (ixj > tid) {
                unsigned a = key[tid], c2 = key[ixj];
                bool up = ((tid & k) == 0);
                if ((a > c2) == up) { key[tid] = c2; key[ixj] = a; }
            }
            __syncthreads();
        }
    }

    int lab     = (int)(key[tid] >> 16);
    int labprev = (tid > 0) ? (int)(key[tid - 1] >> 16) : -1;
    int step = (tid > 0 && tid < CN && lab != labprev) ? 1 : 0;
    sc[tid] = step; __syncthreads();
    for (int off = 1; off < 1024; off <<= 1) {
        int v = (tid >= off) ? sc[tid - off] : 0;
        __syncthreads();
        sc[tid] += v;
        __syncthreads();
    }
    if (tid < CN) {
        int l = sc[tid];
        int orig = (int)(key[tid] & 0xFFFFu);
        labels_out[(size_t)b * CN + orig] = (float)l;
        g_perm[b * CN + tid] = orig;
        if (tid == 0 || step) g_segstart[b * CNP1 + l] = tid;
    }
    __syncthreads();
    if (tid == 0) {
        int ns = sc[CN - 1] + 1;
        g_nseg[b] = ns;
        g_segstart[b * CNP1 + ns] = CN;
    }
}

// -------------------- segment means + cls + pad ------------------------------
__global__ void means_kernel(float* __restrict__ out, const float* __restrict__ cls,
                             const float* __restrict__ pos, const float* __restrict__ pad) {
    int b = blockIdx.y, r = blockIdx.x;
    float* o = out + ((size_t)b * CNP1 + r) * CHD;
    if (r == 0) {
        for (int h = threadIdx.x; h < CHD; h += blockDim.x)
            o[h] = cls[h] + pos[h];
        return;
    }
    int l = r - 1;
    if (l < g_nseg[b]) {
        int s0 = g_segstart[b * CNP1 + l];
        int s1 = g_segstart[b * CNP1 + l + 1];
        float cnt = (float)(s1 - s0);
        for (int h = threadIdx.x; h < CHD; h += blockDim.x) {
            float s = 0.f;
            for (int j = s0; j < s1; j++)
                s += g_emb[((size_t)b * CN + g_perm[b * CN + j]) * CHD + h];
            o[h] = s / cnt;
        }
    } else {
        for (int h = threadIdx.x; h < CHD; h += blockDim.x)
            o[h] = pad[h];
    }
}

// -------------------- attention mask -----------------------------------------
__global__ void attn_kernel(float* __restrict__ attn) {
    size_t idx = (size_t)blockIdx.x * blockDim.x + threadIdx.x;
    size_t total = (size_t)CB * CNP1 * CNP1;
    if (idx >= total) return;
    int j = (int)(idx % CNP1);
    int b = (int)(idx / ((size_t)CNP1 * CNP1));
    float v = 0.0f;
    if (j > 0 && (j - 1) >= g_nseg[b]) v = -3.4028234663852886e38f;  // -FLT_MAX
    attn[idx] = v;
}

// ---------------------------------------------------------------------------
extern "C" void kernel_launch(void* const* d_in, const int* in_sizes, int n_in,
                              void* d_out, int out_size) {
    (void)in_sizes; (void)n_in; (void)out_size;
    const float* px     = (const float*)d_in[0];
    const float* conv_w = (const float*)d_in[1];
    const float* conv_b = (const float*)d_in[2];
    const float* cls    = (const float*)d_in[3];
    const float* pos    = (const float*)d_in[4];
    const float* vocab  = (const float*)d_in[5];
    const float* pad    = (const float*)d_in[6];

    float* out        = (float*)d_out;
    float* labels_out = out + (size_t)CB * CNP1 * CHD;
    float* attn_out   = labels_out + (size_t)CB * CN;

    float *patches, *emb, *scores, *Wt, *vnT;
    cudaGetSymbolAddress((void**)&patches, g_patches);
    cudaGetSymbolAddress((void**)&emb,     g_emb);
    cudaGetSymbolAddress((void**)&scores,  g_scores);
    cudaGetSymbolAddress((void**)&Wt,      g_Wt);
    cudaGetSymbolAddress((void**)&vnT,     g_vnT);

    prep_vocab_kernel<<<CV, 256>>>(vocab);
    transpose_w_kernel<<<dim3(CD / 32, CHD / 32), dim3(32, 32)>>>(conv_w);

    {
        size_t total = (size_t)CBN * CD;
        extract_kernel<<<(unsigned)((total + 255) / 256), 256>>>(px);
    }
    pnorm_kernel<<<CBN, 256>>>();

    // emb = patches @ Wt + conv_b + pos_embed[1:]
    sgemm_kernel<<<dim3((CHD + SG_BN - 1) / SG_BN, CBN / SG_BM), 256>>>(
        patches, Wt, emb, CBN, CHD, CD, conv_b, pos, 1);
    // scores = patches @ vnT  (raw dots vs normalized vocab)
    sgemm_kernel<<<dim3((CV + SG_BN - 1) / SG_BN, CBN / SG_BM), 256>>>(
        patches, vnT, scores, CBN, CV, CD, nullptr, nullptr, 0);

    rowmax_kernel<<<CBN, 256>>>();
    label_scan_kernel<<<1, 1024>>>();
    compact_kernel<<<CB, 1024>>>(labels_out);
    means_kernel<<<dim3(CNP1, CB), 256>>>(out, cls, pos, pad);

    {
        size_t total = (size_t)CB * CNP1 * CNP1;
        attn_kernel<<<(unsigned)((total + 255) / 256), 256>>>(attn_out);
    }
}

// round 4
// speedup vs baseline: 2.1411x; 2.1411x over previous
#include <cuda_runtime.h>
#include <math.h>
#include <stdint.h>

// ---------------------------------------------------------------------------
// InterImageTokenizer — tensor-core round.
//   emb    = patches @ Wt (+bias+pos)  : tf32x3 mma (fp32-class accuracy)
//   scores = patches @ vnT -> fused row max/argmax (single-pass tf32)
// Fixed shapes: B=64, C=3, HW=384, P=16 -> N=576, D=Hd=768, V=1000.
// ---------------------------------------------------------------------------

constexpr int CB   = 64;
constexpr int CC   = 3;
constexpr int CHW  = 384;
constexpr int CP   = 16;
constexpr int CG   = CHW / CP;      // 24
constexpr int CN   = CG * CG;       // 576
constexpr int CD   = CC * CP * CP;  // 768
constexpr int CHD  = 768;
constexpr int CV   = 1000;
constexpr int CBN  = CB * CN;       // 36864
constexpr int CNP1 = CN + 1;        // 577

// -------------------- device scratch ---------------------------------------
__device__ float g_patches[(size_t)CBN * CD];
__device__ float g_emb[(size_t)CBN * CHD];
__device__ float g_Wt[CD * CHD];                  // [d][h]
__device__ float g_vnT[CD * CV];                  // [d][v], vocab normalized
__device__ float g_pnorm[CBN];
__device__ unsigned long long g_packed[CBN];      // (ordered_score<<32)|(~v)
__device__ int   g_labels0[CBN];
__device__ int   g_perm[CB * CN];
__device__ int   g_segstart[CB * CNP1];
__device__ int   g_nseg[CB];

// -------------------- small helpers ----------------------------------------
__device__ __forceinline__ unsigned f2tf32(float x) {
    unsigned r; asm("cvt.rna.tf32.f32 %0, %1;" : "=r"(r) : "f"(x)); return r;
}
__device__ __forceinline__ void mma_tf32(float* c, const unsigned* a, const unsigned* b) {
    asm volatile(
        "mma.sync.aligned.m16n8k8.row.col.f32.tf32.tf32.f32 "
        "{%0,%1,%2,%3}, {%4,%5,%6,%7}, {%8,%9}, {%0,%1,%2,%3};"
        : "+f"(c[0]), "+f"(c[1]), "+f"(c[2]), "+f"(c[3])
        : "r"(a[0]), "r"(a[1]), "r"(a[2]), "r"(a[3]), "r"(b[0]), "r"(b[1]));
}
__device__ __forceinline__ void cp16(void* smem_dst, const void* gmem_src) {
    unsigned s = (unsigned)__cvta_generic_to_shared(smem_dst);
    asm volatile("cp.async.ca.shared.global [%0], [%1], 16;\n" :: "r"(s), "l"(gmem_src));
}
__device__ __forceinline__ unsigned enc_f(float f) {
    unsigned u = __float_as_uint(f);
    return (u & 0x80000000u) ? ~u : (u | 0x80000000u);
}
__device__ __forceinline__ float dec_f(unsigned e) {
    unsigned b = (e & 0x80000000u) ? (e ^ 0x80000000u) : ~e;
    return __uint_as_float(b);
}

// -------------------- prep: normalize vocab (transposed) --------------------
__global__ void prep_vocab_kernel(const float* __restrict__ vocab) {
    int v = blockIdx.x;
    __shared__ float red[256];
    float s = 0.f;
    for (int d = threadIdx.x; d < CD; d += 256) {
        float x = vocab[(size_t)v * CD + d];
        s += x * x;
    }
    red[threadIdx.x] = s; __syncthreads();
    for (int o = 128; o > 0; o >>= 1) {
        if (threadIdx.x < o) red[threadIdx.x] += red[threadIdx.x + o];
        __syncthreads();
    }
    float invn = 1.0f / sqrtf(red[0]);
    for (int d = threadIdx.x; d < CD; d += 256)
        g_vnT[(size_t)d * CV + v] = vocab[(size_t)v * CD + d] * invn;
}

// -------------------- prep: transpose conv weight ---------------------------
__global__ void transpose_w_kernel(const float* __restrict__ W) {
    __shared__ float t[32][33];
    int x = blockIdx.x * 32 + threadIdx.x;  // d
    int y = blockIdx.y * 32 + threadIdx.y;  // h
    t[threadIdx.y][threadIdx.x] = W[(size_t)y * CD + x];
    __syncthreads();
    int xo = blockIdx.y * 32 + threadIdx.x; // h
    int yo = blockIdx.x * 32 + threadIdx.y; // d
    g_Wt[(size_t)yo * CHD + xo] = t[threadIdx.x][threadIdx.y];
}

// -------------------- init packed max --------------------------------------
__global__ void init_packed_kernel() {
    int i = blockIdx.x * 256 + threadIdx.x;
    if (i < CBN) g_packed[i] = 0ULL;
}

// -------------------- fused patch extraction + L2 norm ----------------------
__global__ void __launch_bounds__(256) extract_pnorm_kernel(const float* __restrict__ px) {
    int patch = blockIdx.x;               // 0..CBN-1
    int b = patch / CN, n = patch % CN;
    int hp = n / CG, wp = n % CG;
    const float* base = px + (size_t)b * CC * CHW * CHW;
    int tid = threadIdx.x, lane = tid & 31, w = tid >> 5;
    float ss = 0.f;
#pragma unroll
    for (int j = 0; j < 3; j++) {
        int d = tid + j * 256;
        int c = d >> 8, r = d & 255, ph = r >> 4, pw = r & 15;
        float x = base[((size_t)c * CHW + hp * CP + ph) * CHW + wp * CP + pw];
        g_patches[(size_t)patch * CD + d] = x;
        ss += x * x;
    }
#pragma unroll
    for (int o = 16; o > 0; o >>= 1) ss += __shfl_xor_sync(0xffffffffu, ss, o);
    __shared__ float ws[8];
    if (lane == 0) ws[w] = ss;
    __syncthreads();
    if (tid == 0) {
        float t = 0.f;
#pragma unroll
        for (int i = 0; i < 8; i++) t += ws[i];
        g_pnorm[patch] = sqrtf(t);
    }
}

// -------------------- GEMM config -------------------------------------------
#define BM 128
#define BN 128
#define BK 16
#define AS_ST 20
#define BS_ST 136

// =============== emb GEMM: tf32x3, epilogue bias + pos ======================
__global__ void __launch_bounds__(256, 1)
gemm_emb_kernel(const float* __restrict__ A, const float* __restrict__ Bg,
                float* __restrict__ C, const float* __restrict__ bias,
                const float* __restrict__ pos) {
    __shared__ float As[2][BM][AS_ST];
    __shared__ float Bs[2][BK][BS_ST];
    int tid = threadIdx.x, lane = tid & 31, warp = tid >> 5;
    int warpM = warp >> 2, warpN = warp & 3;
    int rowBase = blockIdx.y * BM, colBase = blockIdx.x * BN;
    int tig = lane & 3, grp = lane >> 2;

    float acc[4][4][4];
#pragma unroll
    for (int mi = 0; mi < 4; mi++)
#pragma unroll
        for (int ni = 0; ni < 4; ni++)
#pragma unroll
            for (int q = 0; q < 4; q++) acc[mi][ni][q] = 0.f;

    const int nk = CD / BK;  // 48

#define EMB_LOAD(ST, K0)                                                            \
    {                                                                               \
        _Pragma("unroll")                                                           \
        for (int i = 0; i < 2; i++) {                                               \
            int idx = tid + i * 256;                                                \
            int r = idx >> 2, k4 = (idx & 3) << 2;                                  \
            cp16(&As[ST][r][k4], &A[(size_t)(rowBase + r) * CD + (K0) + k4]);       \
        }                                                                           \
        _Pragma("unroll")                                                           \
        for (int i = 0; i < 2; i++) {                                               \
            int idx = tid + i * 256;                                                \
            int r = idx >> 5, n4 = (idx & 31) << 2;                                 \
            cp16(&Bs[ST][r][n4], &Bg[(size_t)((K0) + r) * CHD + colBase + n4]);     \
        }                                                                           \
        asm volatile("cp.async.commit_group;\n");                                   \
    }

    EMB_LOAD(0, 0);
    for (int kt = 0; kt < nk; kt++) {
        int st = kt & 1;
        if (kt + 1 < nk) {
            EMB_LOAD(st ^ 1, (kt + 1) * BK);
            asm volatile("cp.async.wait_group 1;\n");
        } else {
            asm volatile("cp.async.wait_group 0;\n");
        }
        __syncthreads();
#pragma unroll
        for (int kk = 0; kk < 2; kk++) {
            int kb = kk * 8;
            unsigned ah[4][4], al[4][4], bh[4][2], bl[4][2];
#pragma unroll
            for (int mi = 0; mi < 4; mi++) {
                int m = warpM * 64 + mi * 16 + grp;
                float a0 = As[st][m][kb + tig];
                float a1 = As[st][m + 8][kb + tig];
                float a2 = As[st][m][kb + tig + 4];
                float a3 = As[st][m + 8][kb + tig + 4];
                ah[mi][0] = f2tf32(a0); al[mi][0] = f2tf32(a0 - __uint_as_float(ah[mi][0]));
                ah[mi][1] = f2tf32(a1); al[mi][1] = f2tf32(a1 - __uint_as_float(ah[mi][1]));
                ah[mi][2] = f2tf32(a2); al[mi][2] = f2tf32(a2 - __uint_as_float(ah[mi][2]));
                ah[mi][3] = f2tf32(a3); al[mi][3] = f2tf32(a3 - __uint_as_float(ah[mi][3]));
            }
#pragma unroll
            for (int ni = 0; ni < 4; ni++) {
                int nn = warpN * 32 + ni * 8 + grp;
                float b0 = Bs[st][kb + tig][nn];
                float b1 = Bs[st][kb + tig + 4][nn];
                bh[ni][0] = f2tf32(b0); bl[ni][0] = f2tf32(b0 - __uint_as_float(bh[ni][0]));
                bh[ni][1] = f2tf32(b1); bl[ni][1] = f2tf32(b1 - __uint_as_float(bh[ni][1]));
            }
#pragma unroll
            for (int mi = 0; mi < 4; mi++)
#pragma unroll
                for (int ni = 0; ni < 4; ni++) {
                    mma_tf32(acc[mi][ni], ah[mi], bh[ni]);
                    mma_tf32(acc[mi][ni], ah[mi], bl[ni]);
                    mma_tf32(acc[mi][ni], al[mi], bh[ni]);
                }
        }
        __syncthreads();
    }
#undef EMB_LOAD

#pragma unroll
    for (int mi = 0; mi < 4; mi++) {
        int r0 = rowBase + warpM * 64 + mi * 16 + grp;
        int r1 = r0 + 8;
        int p0 = (r0 % CN) + 1, p1 = (r1 % CN) + 1;
#pragma unroll
        for (int ni = 0; ni < 4; ni++) {
            int col = colBase + warpN * 32 + ni * 8 + 2 * tig;
            float2 v0, v1;
            v0.x = acc[mi][ni][0] + bias[col]     + pos[(size_t)p0 * CHD + col];
            v0.y = acc[mi][ni][1] + bias[col + 1] + pos[(size_t)p0 * CHD + col + 1];
            v1.x = acc[mi][ni][2] + bias[col]     + pos[(size_t)p1 * CHD + col];
            v1.y = acc[mi][ni][3] + bias[col + 1] + pos[(size_t)p1 * CHD + col + 1];
            *reinterpret_cast<float2*>(&C[(size_t)r0 * CHD + col]) = v0;
            *reinterpret_cast<float2*>(&C[(size_t)r1 * CHD + col]) = v1;
        }
    }
}

// =============== scores GEMM: single tf32, fused max/argmax =================
__global__ void __launch_bounds__(256, 1)
gemm_scores_kernel(const float* __restrict__ A, const float* __restrict__ Bg) {
    __shared__ float As[2][BM][AS_ST];
    __shared__ float Bs[2][BK][BS_ST];
    int tid = threadIdx.x, lane = tid & 31, warp = tid >> 5;
    int warpM = warp >> 2, warpN = warp & 3;
    int rowBase = blockIdx.y * BM, colBase = blockIdx.x * BN;
    int tig = lane & 3, grp = lane >> 2;

    float acc[4][4][4];
#pragma unroll
    for (int mi = 0; mi < 4; mi++)
#pragma unroll
        for (int ni = 0; ni < 4; ni++)
#pragma unroll
            for (int q = 0; q < 4; q++) acc[mi][ni][q] = 0.f;

    const int nk = CD / BK;

#define SC_LOAD(ST, K0)                                                              \
    {                                                                                \
        _Pragma("unroll")                                                            \
        for (int i = 0; i < 2; i++) {                                                \
            int idx = tid + i * 256;                                                 \
            int r = idx >> 2, k4 = (idx & 3) << 2;                                   \
            cp16(&As[ST][r][k4], &A[(size_t)(rowBase + r) * CD + (K0) + k4]);        \
        }                                                                            \
        _Pragma("unroll")                                                            \
        for (int i = 0; i < 2; i++) {                                                \
            int idx = tid + i * 256;                                                 \
            int r = idx >> 5, n4 = (idx & 31) << 2;                                  \
            int gc = colBase + n4;                                                   \
            if (gc < CV) {                                                           \
                cp16(&Bs[ST][r][n4], &Bg[(size_t)((K0) + r) * CV + gc]);             \
            } else {                                                                 \
                *reinterpret_cast<float4*>(&Bs[ST][r][n4]) =                         \
                    make_float4(0.f, 0.f, 0.f, 0.f);                                 \
            }                                                                        \
        }                                                                            \
        asm volatile("cp.async.commit_group;\n");                                    \
    }

    SC_LOAD(0, 0);
    for (int kt = 0; kt < nk; kt++) {
        int st = kt & 1;
        if (kt + 1 < nk) {
            SC_LOAD(st ^ 1, (kt + 1) * BK);
            asm volatile("cp.async.wait_group 1;\n");
        } else {
            asm volatile("cp.async.wait_group 0;\n");
        }
        __syncthreads();
#pragma unroll
        for (int kk = 0; kk < 2; kk++) {
            int kb = kk * 8;
            unsigned ua[4][4], ub[4][2];
#pragma unroll
            for (int mi = 0; mi < 4; mi++) {
                int m = warpM * 64 + mi * 16 + grp;
                ua[mi][0] = f2tf32(As[st][m][kb + tig]);
                ua[mi][1] = f2tf32(As[st][m + 8][kb + tig]);
                ua[mi][2] = f2tf32(As[st][m][kb + tig + 4]);
                ua[mi][3] = f2tf32(As[st][m + 8][kb + tig + 4]);
            }
#pragma unroll
            for (int ni = 0; ni < 4; ni++) {
                int nn = warpN * 32 + ni * 8 + grp;
                ub[ni][0] = f2tf32(Bs[st][kb + tig][nn]);
                ub[ni][1] = f2tf32(Bs[st][kb + tig + 4][nn]);
            }
#pragma unroll
            for (int mi = 0; mi < 4; mi++)
#pragma unroll
                for (int ni = 0; ni < 4; ni++)
                    mma_tf32(acc[mi][ni], ua[mi], ub[ni]);
        }
        __syncthreads();
    }
#undef SC_LOAD

    // fused per-row max/argmax (ties -> smallest v, matching argmin-first)
#pragma unroll
    for (int mi = 0; mi < 4; mi++) {
#pragma unroll
        for (int h = 0; h < 2; h++) {
            int row = rowBase + warpM * 64 + mi * 16 + h * 8 + grp;
            unsigned long long p = 0ULL;
#pragma unroll
            for (int ni = 0; ni < 4; ni++) {
                int col = colBase + warpN * 32 + ni * 8 + 2 * tig;
                float s0 = acc[mi][ni][h * 2 + 0];
                float s1 = acc[mi][ni][h * 2 + 1];
                if (col < CV) {
                    unsigned long long q =
                        ((unsigned long long)enc_f(s0) << 32) | (0xFFFFFFFFu - (unsigned)col);
                    if (q > p) p = q;
                }
                if (col + 1 < CV) {
                    unsigned long long q =
                        ((unsigned long long)enc_f(s1) << 32) | (0xFFFFFFFFu - (unsigned)(col + 1));
                    if (q > p) p = q;
                }
            }
            unsigned long long o;
            o = __shfl_xor_sync(0xffffffffu, p, 1); if (o > p) p = o;
            o = __shfl_xor_sync(0xffffffffu, p, 2); if (o > p) p = o;
            if (tig == 0) atomicMax(&g_packed[row], p);
        }
    }
}

// -------------------- mask + global scan -> raw labels ----------------------
__global__ void __launch_bounds__(1024) label_scan_kernel() {
    __shared__ int wsum[32];
    int tid = threadIdx.x, lane = tid & 31, w = tid >> 5;
    int running = 0;
    for (int base = 0; base < CBN; base += 1024) {
        int i = base + tid;
        unsigned long long p = g_packed[i];
        float score = dec_f((unsigned)(p >> 32));
        int v = (int)(0xFFFFFFFFu - (unsigned)(p & 0xFFFFFFFFu));
        float smin = 1.0f - score / g_pnorm[i];
        int m = (smin > 0.1f) ? 1 : 0;
        int x = m;
#pragma unroll
        for (int off = 1; off < 32; off <<= 1) {
            int y = __shfl_up_sync(0xffffffffu, x, off);
            if (lane >= off) x += y;
        }
        if (lane == 31) wsum[w] = x;
        __syncthreads();
        if (w == 0) {
            int s = wsum[lane];
#pragma unroll
            for (int off = 1; off < 32; off <<= 1) {
                int y = __shfl_up_sync(0xffffffffu, s, off);
                if (lane >= off) s += y;
            }
            wsum[lane] = s;
        }
        __syncthreads();
        int incl = x + ((w > 0) ? wsum[w - 1] : 0);
        int excl = incl - m;
        g_labels0[i] = m ? (CV + running + excl) : v;
        running += wsum[31];
        __syncthreads();
    }
}

// -------------------- per-row bitonic sort + unique-consecutive --------------
__global__ void __launch_bounds__(1024)
compact_kernel(float* __restrict__ labels_out) {
    __shared__ unsigned int key[1024];
    __shared__ int sc[1024];
    int b = blockIdx.x, tid = threadIdx.x;
    key[tid] = (tid < CN) ? ((((unsigned)g_labels0[b * CN + tid]) << 16) | (unsigned)tid)
                          : 0xFFFFFFFFu;
    __syncthreads();

    for (int k = 2; k <= 1024; k <<= 1) {
        for (int j = k >> 1; j > 0; j >>= 1) {
            int ixj = tid ^ j;
            if (ixj > tid) {
                unsigned a = key[tid], c2 = key[ixj];
                bool up = ((tid & k) == 0);
                if ((a > c2) == up) { key[tid] = c2; key[ixj] = a; }
            }
            __syncthreads();
        }
    }

    int lab     = (int)(key[tid] >> 16);
    int labprev = (tid > 0) ? (int)(key[tid - 1] >> 16) : -1;
    int step = (tid > 0 && tid < CN && lab != labprev) ? 1 : 0;
    sc[tid] = step; __syncthreads();
    for (int off = 1; off < 1024; off <<= 1) {
        int v = (tid >= off) ? sc[tid - off] : 0;
        __syncthreads();
        sc[tid] += v;
        __syncthreads();
    }
    if (tid < CN) {
        int l = sc[tid];
        int orig = (int)(key[tid] & 0xFFFFu);
        labels_out[(size_t)b * CN + orig] = (float)l;
        g_perm[b * CN + tid] = orig;
        if (tid == 0 || step) g_segstart[b * CNP1 + l] = tid;
    }
    __syncthreads();
    if (tid == 0) {
        int ns = sc[CN - 1] + 1;
        g_nseg[b] = ns;
        g_segstart[b * CNP1 + ns] = CN;
    }
}

// -------------------- segment means + cls + pad ------------------------------
__global__ void means_kernel(float* __restrict__ out, const float* __restrict__ cls,
                             const float* __restrict__ pos, const float* __restrict__ pad) {
    int b = blockIdx.y, r = blockIdx.x;
    float* o = out + ((size_t)b * CNP1 + r) * CHD;
    if (r == 0) {
        for (int h = threadIdx.x; h < CHD; h += blockDim.x)
            o[h] = cls[h] + pos[h];
        return;
    }
    int l = r - 1;
    if (l < g_nseg[b]) {
        int s0 = g_segstart[b * CNP1 + l];
        int s1 = g_segstart[b * CNP1 + l + 1];
        float cnt = (float)(s1 - s0);
        for (int h = threadIdx.x; h < CHD; h += blockDim.x) {
            float s = 0.f;
            for (int j = s0; j < s1; j++)
                s += g_emb[((size_t)b * CN + g_perm[b * CN + j]) * CHD + h];
            o[h] = s / cnt;
        }
    } else {
        for (int h = threadIdx.x; h < CHD; h += blockDim.x)
            o[h] = pad[h];
    }
}

// -------------------- attention mask -----------------------------------------
__global__ void attn_kernel(float* __restrict__ attn) {
    size_t idx = (size_t)blockIdx.x * blockDim.x + threadIdx.x;
    size_t total = (size_t)CB * CNP1 * CNP1;
    if (idx >= total) return;
    int j = (int)(idx % CNP1);
    int b = (int)(idx / ((size_t)CNP1 * CNP1));
    float v = 0.0f;
    if (j > 0 && (j - 1) >= g_nseg[b]) v = -3.4028234663852886e38f;  // -FLT_MAX
    attn[idx] = v;
}

// ---------------------------------------------------------------------------
extern "C" void kernel_launch(void* const* d_in, const int* in_sizes, int n_in,
                              void* d_out, int out_size) {
    (void)in_sizes; (void)n_in; (void)out_size;
    const float* px     = (const float*)d_in[0];
    const float* conv_w = (const float*)d_in[1];
    const float* conv_b = (const float*)d_in[2];
    const float* cls    = (const float*)d_in[3];
    const float* pos    = (const float*)d_in[4];
    const float* vocab  = (const float*)d_in[5];
    const float* pad    = (const float*)d_in[6];

    float* out        = (float*)d_out;
    float* labels_out = out + (size_t)CB * CNP1 * CHD;
    float* attn_out   = labels_out + (size_t)CB * CN;

    float *patches, *emb, *Wt, *vnT;
    cudaGetSymbolAddress((void**)&patches, g_patches);
    cudaGetSymbolAddress((void**)&emb,     g_emb);
    cudaGetSymbolAddress((void**)&Wt,      g_Wt);
    cudaGetSymbolAddress((void**)&vnT,     g_vnT);

    init_packed_kernel<<<(CBN + 255) / 256, 256>>>();
    prep_vocab_kernel<<<CV, 256>>>(vocab);
    transpose_w_kernel<<<dim3(CD / 32, CHD / 32), dim3(32, 32)>>>(conv_w);
    extract_pnorm_kernel<<<CBN, 256>>>(px);

    gemm_emb_kernel<<<dim3(CHD / BN, CBN / BM), 256>>>(patches, Wt, emb, conv_b, pos);
    gemm_scores_kernel<<<dim3((CV + BN - 1) / BN, CBN / BM), 256>>>(patches, vnT);

    label_scan_kernel<<<1, 1024>>>();
    compact_kernel<<<CB, 1024>>>(labels_out);
    means_kernel<<<dim3(CNP1, CB), 256>>>(out, cls, pos, pad);

    {
        size_t total = (size_t)CB * CNP1 * CNP1;
        attn_kernel<<<(unsigned)((total + 255) / 256), 256>>>(attn_out);
    }
}

// round 5
// speedup vs baseline: 3.1146x; 1.4547x over previous
#include <cuda_runtime.h>
#include <math.h>
#include <stdint.h>

// ---------------------------------------------------------------------------
// InterImageTokenizer — tensor-core round 2 (single-pass tf32, pre-rounded
// operands, no inner-loop cvt, 2 CTAs/SM).
// Fixed shapes: B=64, C=3, HW=384, P=16 -> N=576, D=Hd=768, V=1000.
// ---------------------------------------------------------------------------

constexpr int CB   = 64;
constexpr int CC   = 3;
constexpr int CHW  = 384;
constexpr int CP   = 16;
constexpr int CG   = CHW / CP;      // 24
constexpr int CN   = CG * CG;       // 576
constexpr int CD   = CC * CP * CP;  // 768
constexpr int CHD  = 768;
constexpr int CV   = 1000;
constexpr int CBN  = CB * CN;       // 36864
constexpr int CNP1 = CN + 1;        // 577

// -------------------- device scratch ---------------------------------------
__device__ float g_patches[(size_t)CBN * CD];     // tf32-rounded
__device__ float g_emb[(size_t)CBN * CHD];
__device__ float g_Wt[CD * CHD];                  // [d][h], tf32-rounded
__device__ float g_vnT[CD * CV];                  // [d][v], normalized + tf32-rounded
__device__ float g_pnorm[CBN];
__device__ unsigned long long g_packed[CBN];      // (ordered_score<<32)|(~v)
__device__ int   g_labels0[CBN];
__device__ int   g_perm[CB * CN];
__device__ int   g_segstart[CB * CNP1];
__device__ int   g_nseg[CB];

// -------------------- small helpers ----------------------------------------
__device__ __forceinline__ float round_tf32(float x) {
    unsigned r; asm("cvt.rna.tf32.f32 %0, %1;" : "=r"(r) : "f"(x));
    return __uint_as_float(r);
}
__device__ __forceinline__ void mma_tf32(float* c, const unsigned* a, const unsigned* b) {
    asm volatile(
        "mma.sync.aligned.m16n8k8.row.col.f32.tf32.tf32.f32 "
        "{%0,%1,%2,%3}, {%4,%5,%6,%7}, {%8,%9}, {%0,%1,%2,%3};"
        : "+f"(c[0]), "+f"(c[1]), "+f"(c[2]), "+f"(c[3])
        : "r"(a[0]), "r"(a[1]), "r"(a[2]), "r"(a[3]), "r"(b[0]), "r"(b[1]));
}
__device__ __forceinline__ void cp16(void* smem_dst, const void* gmem_src) {
    unsigned s = (unsigned)__cvta_generic_to_shared(smem_dst);
    asm volatile("cp.async.ca.shared.global [%0], [%1], 16;\n" :: "r"(s), "l"(gmem_src));
}
__device__ __forceinline__ unsigned enc_f(float f) {
    unsigned u = __float_as_uint(f);
    return (u & 0x80000000u) ? ~u : (u | 0x80000000u);
}
__device__ __forceinline__ float dec_f(unsigned e) {
    unsigned b = (e & 0x80000000u) ? (e ^ 0x80000000u) : ~e;
    return __uint_as_float(b);
}

// -------------------- prep: normalize vocab (transposed, tf32-rounded) ------
__global__ void prep_vocab_kernel(const float* __restrict__ vocab) {
    int v = blockIdx.x;
    __shared__ float red[256];
    float s = 0.f;
    for (int d = threadIdx.x; d < CD; d += 256) {
        float x = vocab[(size_t)v * CD + d];
        s += x * x;
    }
    red[threadIdx.x] = s; __syncthreads();
    for (int o = 128; o > 0; o >>= 1) {
        if (threadIdx.x < o) red[threadIdx.x] += red[threadIdx.x + o];
        __syncthreads();
    }
    float invn = 1.0f / sqrtf(red[0]);
    for (int d = threadIdx.x; d < CD; d += 256)
        g_vnT[(size_t)d * CV + v] = round_tf32(vocab[(size_t)v * CD + d] * invn);
}

// -------------------- prep: transpose conv weight (tf32-rounded) -------------
__global__ void transpose_w_kernel(const float* __restrict__ W) {
    __shared__ float t[32][33];
    int x = blockIdx.x * 32 + threadIdx.x;  // d
    int y = blockIdx.y * 32 + threadIdx.y;  // h
    t[threadIdx.y][threadIdx.x] = W[(size_t)y * CD + x];
    __syncthreads();
    int xo = blockIdx.y * 32 + threadIdx.x; // h
    int yo = blockIdx.x * 32 + threadIdx.y; // d
    g_Wt[(size_t)yo * CHD + xo] = round_tf32(t[threadIdx.x][threadIdx.y]);
}

// -------------------- init packed max --------------------------------------
__global__ void init_packed_kernel() {
    int i = blockIdx.x * 256 + threadIdx.x;
    if (i < CBN) g_packed[i] = 0ULL;
}

// -------------------- fused patch extraction + L2 norm (tf32-rounded) --------
__global__ void __launch_bounds__(256) extract_pnorm_kernel(const float* __restrict__ px) {
    int patch = blockIdx.x;               // 0..CBN-1
    int b = patch / CN, n = patch % CN;
    int hp = n / CG, wp = n % CG;
    const float* base = px + (size_t)b * CC * CHW * CHW;
    int tid = threadIdx.x, lane = tid & 31, w = tid >> 5;
    float ss = 0.f;
#pragma unroll
    for (int j = 0; j < 3; j++) {
        int d = tid + j * 256;
        int c = d >> 8, r = d & 255, ph = r >> 4, pw = r & 15;
        float x = base[((size_t)c * CHW + hp * CP + ph) * CHW + wp * CP + pw];
        g_patches[(size_t)patch * CD + d] = round_tf32(x);
        ss += x * x;
    }
#pragma unroll
    for (int o = 16; o > 0; o >>= 1) ss += __shfl_xor_sync(0xffffffffu, ss, o);
    __shared__ float ws[8];
    if (lane == 0) ws[w] = ss;
    __syncthreads();
    if (tid == 0) {
        float t = 0.f;
#pragma unroll
        for (int i = 0; i < 8; i++) t += ws[i];
        g_pnorm[patch] = sqrtf(t);
    }
}

// -------------------- GEMM config -------------------------------------------
#define BM 128
#define BN 128
#define BK 16
#define AS_ST 20
#define BS_ST 136

// =============== emb GEMM: single tf32, epilogue bias + pos =================
__global__ void __launch_bounds__(256, 2)
gemm_emb_kernel(const float* __restrict__ A, const float* __restrict__ Bg,
                float* __restrict__ C, const float* __restrict__ bias,
                const float* __restrict__ pos) {
    __shared__ float As[2][BM][AS_ST];
    __shared__ float Bs[2][BK][BS_ST];
    int tid = threadIdx.x, lane = tid & 31, warp = tid >> 5;
    int warpM = warp >> 2, warpN = warp & 3;
    int rowBase = blockIdx.y * BM, colBase = blockIdx.x * BN;
    int tig = lane & 3, grp = lane >> 2;

    float acc[4][4][4];
#pragma unroll
    for (int mi = 0; mi < 4; mi++)
#pragma unroll
        for (int ni = 0; ni < 4; ni++)
#pragma unroll
            for (int q = 0; q < 4; q++) acc[mi][ni][q] = 0.f;

    const int nk = CD / BK;  // 48

#define EMB_LOAD(ST, K0)                                                            \
    {                                                                               \
        _Pragma("unroll")                                                           \
        for (int i = 0; i < 2; i++) {                                               \
            int idx = tid + i * 256;                                                \
            int r = idx >> 2, k4 = (idx & 3) << 2;                                  \
            cp16(&As[ST][r][k4], &A[(size_t)(rowBase + r) * CD + (K0) + k4]);       \
        }                                                                           \
        _Pragma("unroll")                                                           \
        for (int i = 0; i < 2; i++) {                                               \
            int idx = tid + i * 256;                                                \
            int r = idx >> 5, n4 = (idx & 31) << 2;                                 \
            cp16(&Bs[ST][r][n4], &Bg[(size_t)((K0) + r) * CHD + colBase + n4]);     \
        }                                                                           \
        asm volatile("cp.async.commit_group;\n");                                   \
    }

    EMB_LOAD(0, 0);
    for (int kt = 0; kt < nk; kt++) {
        int st = kt & 1;
        if (kt + 1 < nk) {
            EMB_LOAD(st ^ 1, (kt + 1) * BK);
            asm volatile("cp.async.wait_group 1;\n");
        } else {
            asm volatile("cp.async.wait_group 0;\n");
        }
        __syncthreads();
#pragma unroll
        for (int kk = 0; kk < 2; kk++) {
            int kb = kk * 8;
            unsigned ua[4][4], ub[4][2];
#pragma unroll
            for (int mi = 0; mi < 4; mi++) {
                int m = warpM * 64 + mi * 16 + grp;
                ua[mi][0] = __float_as_uint(As[st][m][kb + tig]);
                ua[mi][1] = __float_as_uint(As[st][m + 8][kb + tig]);
                ua[mi][2] = __float_as_uint(As[st][m][kb + tig + 4]);
                ua[mi][3] = __float_as_uint(As[st][m + 8][kb + tig + 4]);
            }
#pragma unroll
            for (int ni = 0; ni < 4; ni++) {
                int nn = warpN * 32 + ni * 8 + grp;
                ub[ni][0] = __float_as_uint(Bs[st][kb + tig][nn]);
                ub[ni][1] = __float_as_uint(Bs[st][kb + tig + 4][nn]);
            }
#pragma unroll
            for (int mi = 0; mi < 4; mi++)
#pragma unroll
                for (int ni = 0; ni < 4; ni++)
                    mma_tf32(acc[mi][ni], ua[mi], ub[ni]);
        }
        __syncthreads();
    }
#undef EMB_LOAD

#pragma unroll
    for (int mi = 0; mi < 4; mi++) {
        int r0 = rowBase + warpM * 64 + mi * 16 + grp;
        int r1 = r0 + 8;
        int p0 = (r0 % CN) + 1, p1 = (r1 % CN) + 1;
#pragma unroll
        for (int ni = 0; ni < 4; ni++) {
            int col = colBase + warpN * 32 + ni * 8 + 2 * tig;
            float2 v0, v1;
            v0.x = acc[mi][ni][0] + bias[col]     + pos[(size_t)p0 * CHD + col];
            v0.y = acc[mi][ni][1] + bias[col + 1] + pos[(size_t)p0 * CHD + col + 1];
            v1.x = acc[mi][ni][2] + bias[col]     + pos[(size_t)p1 * CHD + col];
            v1.y = acc[mi][ni][3] + bias[col + 1] + pos[(size_t)p1 * CHD + col + 1];
            *reinterpret_cast<float2*>(&C[(size_t)r0 * CHD + col]) = v0;
            *reinterpret_cast<float2*>(&C[(size_t)r1 * CHD + col]) = v1;
        }
    }
}

// =============== scores GEMM: single tf32, fused max/argmax =================
__global__ void __launch_bounds__(256, 2)
gemm_scores_kernel(const float* __restrict__ A, const float* __restrict__ Bg) {
    __shared__ float As[2][BM][AS_ST];
    __shared__ float Bs[2][BK][BS_ST];
    int tid = threadIdx.x, lane = tid & 31, warp = tid >> 5;
    int warpM = warp >> 2, warpN = warp & 3;
    int rowBase = blockIdx.y * BM, colBase = blockIdx.x * BN;
    int tig = lane & 3, grp = lane >> 2;

    float acc[4][4][4];
#pragma unroll
    for (int mi = 0; mi < 4; mi++)
#pragma unroll
        for (int ni = 0; ni < 4; ni++)
#pragma unroll
            for (int q = 0; q < 4; q++) acc[mi][ni][q] = 0.f;

    const int nk = CD / BK;

#define SC_LOAD(ST, K0)                                                              \
    {                                                                                \
        _Pragma("unroll")                                                            \
        for (int i = 0; i < 2; i++) {                                                \
            int idx = tid + i * 256;                                                 \
            int r = idx >> 2, k4 = (idx & 3) << 2;                                   \
            cp16(&As[ST][r][k4], &A[(size_t)(rowBase + r) * CD + (K0) + k4]);        \
        }                                                                            \
        _Pragma("unroll")                                                            \
        for (int i = 0; i < 2; i++) {                                                \
            int idx = tid + i * 256;                                                 \
            int r = idx >> 5, n4 = (idx & 31) << 2;                                  \
            int gc = colBase + n4;                                                   \
            if (gc < CV) {                                                           \
                cp16(&Bs[ST][r][n4], &Bg[(size_t)((K0) + r) * CV + gc]);             \
            } else {                                                                 \
                *reinterpret_cast<float4*>(&Bs[ST][r][n4]) =                         \
                    make_float4(0.f, 0.f, 0.f, 0.f);                                 \
            }                                                                        \
        }                                                                            \
        asm volatile("cp.async.commit_group;\n");                                    \
    }

    SC_LOAD(0, 0);
    for (int kt = 0; kt < nk; kt++) {
        int st = kt & 1;
        if (kt + 1 < nk) {
            SC_LOAD(st ^ 1, (kt + 1) * BK);
            asm volatile("cp.async.wait_group 1;\n");
        } else {
            asm volatile("cp.async.wait_group 0;\n");
        }
        __syncthreads();
#pragma unroll
        for (int kk = 0; kk < 2; kk++) {
            int kb = kk * 8;
            unsigned ua[4][4], ub[4][2];
#pragma unroll
            for (int mi = 0; mi < 4; mi++) {
                int m = warpM * 64 + mi * 16 + grp;
                ua[mi][0] = __float_as_uint(As[st][m][kb + tig]);
                ua[mi][1] = __float_as_uint(As[st][m + 8][kb + tig]);
                ua[mi][2] = __float_as_uint(As[st][m][kb + tig + 4]);
                ua[mi][3] = __float_as_uint(As[st][m + 8][kb + tig + 4]);
            }
#pragma unroll
            for (int ni = 0; ni < 4; ni++) {
                int nn = warpN * 32 + ni * 8 + grp;
                ub[ni][0] = __float_as_uint(Bs[st][kb + tig][nn]);
                ub[ni][1] = __float_as_uint(Bs[st][kb + tig + 4][nn]);
            }
#pragma unroll
            for (int mi = 0; mi < 4; mi++)
#pragma unroll
                for (int ni = 0; ni < 4; ni++)
                    mma_tf32(acc[mi][ni], ua[mi], ub[ni]);
        }
        __syncthreads();
    }
#undef SC_LOAD

    // fused per-row max/argmax (ties -> smallest v, matching argmin-first)
#pragma unroll
    for (int mi = 0; mi < 4; mi++) {
#pragma unroll
        for (int h = 0; h < 2; h++) {
            int row = rowBase + warpM * 64 + mi * 16 + h * 8 + grp;
            unsigned long long p = 0ULL;
#pragma unroll
            for (int ni = 0; ni < 4; ni++) {
                int col = colBase + warpN * 32 + ni * 8 + 2 * tig;
                float s0 = acc[mi][ni][h * 2 + 0];
                float s1 = acc[mi][ni][h * 2 + 1];
                if (col < CV) {
                    unsigned long long q =
                        ((unsigned long long)enc_f(s0) << 32) | (0xFFFFFFFFu - (unsigned)col);
                    if (q > p) p = q;
                }
                if (col + 1 < CV) {
                    unsigned long long q =
                        ((unsigned long long)enc_f(s1) << 32) | (0xFFFFFFFFu - (unsigned)(col + 1));
                    if (q > p) p = q;
                }
            }
            unsigned long long o;
            o = __shfl_xor_sync(0xffffffffu, p, 1); if (o > p) p = o;
            o = __shfl_xor_sync(0xffffffffu, p, 2); if (o > p) p = o;
            if (tig == 0) atomicMax(&g_packed[row], p);
        }
    }
}

// -------------------- mask + global scan -> raw labels ----------------------
__global__ void __launch_bounds__(1024) label_scan_kernel() {
    __shared__ int wsum[32];
    int tid = threadIdx.x, lane = tid & 31, w = tid >> 5;
    int running = 0;
    for (int base = 0; base < CBN; base += 1024) {
        int i = base + tid;
        unsigned long long p = g_packed[i];
        float score = dec_f((unsigned)(p >> 32));
        int v = (int)(0xFFFFFFFFu - (unsigned)(p & 0xFFFFFFFFu));
        float smin = 1.0f - score / g_pnorm[i];
        int m = (smin > 0.1f) ? 1 : 0;
        int x = m;
#pragma unroll
        for (int off = 1; off < 32; off <<= 1) {
            int y = __shfl_up_sync(0xffffffffu, x, off);
            if (lane >= off) x += y;
        }
        if (lane == 31) wsum[w] = x;
        __syncthreads();
        if (w == 0) {
            int s = wsum[lane];
#pragma unroll
            for (int off = 1; off < 32; off <<= 1) {
                int y = __shfl_up_sync(0xffffffffu, s, off);
                if (lane >= off) s += y;
            }
            wsum[lane] = s;
        }
        __syncthreads();
        int incl = x + ((w > 0) ? wsum[w - 1] : 0);
        int excl = incl - m;
        g_labels0[i] = m ? (CV + running + excl) : v;
        running += wsum[31];
        __syncthreads();
    }
}

// -------------------- per-row bitonic sort + unique-consecutive --------------
__global__ void __launch_bounds__(1024)
compact_kernel(float* __restrict__ labels_out) {
    __shared__ unsigned int key[1024];
    __shared__ int sc[1024];
    int b = blockIdx.x, tid = threadIdx.x;
    key[tid] = (tid < CN) ? ((((unsigned)g_labels0[b * CN + tid]) << 16) | (unsigned)tid)
                          : 0xFFFFFFFFu;
    __syncthreads();

    for (int k = 2; k <= 1024; k <<= 1) {
        for (int j = k >> 1; j > 0; j >>= 1) {
            int ixj = tid ^ j;
            if (ixj > tid) {
                unsigned a = key[tid], c2 = key[ixj];
                bool up = ((tid & k) == 0);
                if ((a > c2) == up) { key[tid] = c2; key[ixj] = a; }
            }
            __syncthreads();
        }
    }

    int lab     = (int)(key[tid] >> 16);
    int labprev = (tid > 0) ? (int)(key[tid - 1] >> 16) : -1;
    int step = (tid > 0 && tid < CN && lab != labprev) ? 1 : 0;
    sc[tid] = step; __syncthreads();
    for (int off = 1; off < 1024; off <<= 1) {
        int v = (tid >= off) ? sc[tid - off] : 0;
        __syncthreads();
        sc[tid] += v;
        __syncthreads();
    }
    if (tid < CN) {
        int l = sc[tid];
        int orig = (int)(key[tid] & 0xFFFFu);
        labels_out[(size_t)b * CN + orig] = (float)l;
        g_perm[b * CN + tid] = orig;
        if (tid == 0 || step) g_segstart[b * CNP1 + l] = tid;
    }
    __syncthreads();
    if (tid == 0) {
        int ns = sc[CN - 1] + 1;
        g_nseg[b] = ns;
        g_segstart[b * CNP1 + ns] = CN;
    }
}

// -------------------- segment means + cls + pad ------------------------------
__global__ void means_kernel(float* __restrict__ out, const float* __restrict__ cls,
                             const float* __restrict__ pos, const float* __restrict__ pad) {
    int b = blockIdx.y, r = blockIdx.x;
    float* o = out + ((size_t)b * CNP1 + r) * CHD;
    if (r == 0) {
        for (int h = threadIdx.x; h < CHD; h += blockDim.x)
            o[h] = cls[h] + pos[h];
        return;
    }
    int l = r - 1;
    if (l < g_nseg[b]) {
        int s0 = g_segstart[b * CNP1 + l];
        int s1 = g_segstart[b * CNP1 + l + 1];
        float cnt = (float)(s1 - s0);
        for (int h = threadIdx.x; h < CHD; h += blockDim.x) {
            float s = 0.f;
            for (int j = s0; j < s1; j++)
                s += g_emb[((size_t)b * CN + g_perm[b * CN + j]) * CHD + h];
            o[h] = s / cnt;
        }
    } else {
        for (int h = threadIdx.x; h < CHD; h += blockDim.x)
            o[h] = pad[h];
    }
}

// -------------------- attention mask -----------------------------------------
__global__ void attn_kernel(float* __restrict__ attn) {
    size_t idx = (size_t)blockIdx.x * blockDim.x + threadIdx.x;
    size_t total = (size_t)CB * CNP1 * CNP1;
    if (idx >= total) return;
    int j = (int)(idx % CNP1);
    int b = (int)(idx / ((size_t)CNP1 * CNP1));
    float v = 0.0f;
    if (j > 0 && (j - 1) >= g_nseg[b]) v = -3.4028234663852886e38f;  // -FLT_MAX
    attn[idx] = v;
}

// ---------------------------------------------------------------------------
extern "C" void kernel_launch(void* const* d_in, const int* in_sizes, int n_in,
                              void* d_out, int out_size) {
    (void)in_sizes; (void)n_in; (void)out_size;
    const float* px     = (const float*)d_in[0];
    const float* conv_w = (const float*)d_in[1];
    const float* conv_b = (const float*)d_in[2];
    const float* cls    = (const float*)d_in[3];
    const float* pos    = (const float*)d_in[4];
    const float* vocab  = (const float*)d_in[5];
    const float* pad    = (const float*)d_in[6];

    float* out        = (float*)d_out;
    float* labels_out = out + (size_t)CB * CNP1 * CHD;
    float* attn_out   = labels_out + (size_t)CB * CN;

    float *patches, *emb, *Wt, *vnT;
    cudaGetSymbolAddress((void**)&patches, g_patches);
    cudaGetSymbolAddress((void**)&emb,     g_emb);
    cudaGetSymbolAddress((void**)&Wt,      g_Wt);
    cudaGetSymbolAddress((void**)&vnT,     g_vnT);

    init_packed_kernel<<<(CBN + 255) / 256, 256>>>();
    prep_vocab_kernel<<<CV, 256>>>(vocab);
    transpose_w_kernel<<<dim3(CD / 32, CHD / 32), dim3(32, 32)>>>(conv_w);
    extract_pnorm_kernel<<<CBN, 256>>>(px);

    gemm_emb_kernel<<<dim3(CHD / BN, CBN / BM), 256>>>(patches, Wt, emb, conv_b, pos);
    gemm_scores_kernel<<<dim3((CV + BN - 1) / BN, CBN / BM), 256>>>(patches, vnT);

    label_scan_kernel<<<1, 1024>>>();
    compact_kernel<<<CB, 1024>>>(labels_out);
    means_kernel<<<dim3(CNP1, CB), 256>>>(out, cls, pos, pad);

    {
        size_t total = (size_t)CB * CNP1 * CNP1;
        attn_kernel<<<(unsigned)((total + 255) / 256), 256>>>(attn_out);
    }
}

// round 8
// speedup vs baseline: 4.6036x; 1.4781x over previous
#include <cuda_runtime.h>
#include <cuda_fp16.h>
#include <math.h>
#include <stdint.h>

// ---------------------------------------------------------------------------
// InterImageTokenizer — fp16 m16n8k16 mma round (tcgen05 unavailable: harness
// PTX stage targets compute_103 which rejects tcgen05).
// Fixed shapes: B=64, C=3, HW=384, P=16 -> N=576, D=Hd=768, V=1000.
// ---------------------------------------------------------------------------

constexpr int CB   = 64;
constexpr int CC   = 3;
constexpr int CHW  = 384;
constexpr int CP   = 16;
constexpr int CG   = CHW / CP;      // 24
constexpr int CN   = CG * CG;       // 576
constexpr int CD   = CC * CP * CP;  // 768
constexpr int CHD  = 768;
constexpr int CV   = 1000;
constexpr int CVP  = 1024;          // padded vocab rows
constexpr int CBN  = CB * CN;       // 36864
constexpr int CNP1 = CN + 1;        // 577

// -------------------- device scratch ---------------------------------------
__device__ __half g_patches[(size_t)CBN * CD];    // fp16, [M][K]
__device__ float  g_emb[(size_t)CBN * CHD];
__device__ __half g_Wh[CHD * CD];                 // conv_w fp16, [h][d] K-major
__device__ __half g_vn[(size_t)CVP * CD];         // normalized vocab fp16, padded
__device__ float  g_pnorm[CBN];
__device__ unsigned long long g_packed[CBN];      // (ordered_score<<32)|(~v)
__device__ int   g_labels0[CBN];
__device__ int   g_perm[CB * CN];
__device__ int   g_segstart[CB * CNP1];
__device__ int   g_nseg[CB];

// -------------------- helpers ----------------------------------------------
__device__ __forceinline__ void mma_f16(float* c, const unsigned* a, const unsigned* b) {
    asm volatile(
        "mma.sync.aligned.m16n8k16.row.col.f32.f16.f16.f32 "
        "{%0,%1,%2,%3}, {%4,%5,%6,%7}, {%8,%9}, {%0,%1,%2,%3};"
        : "+f"(c[0]), "+f"(c[1]), "+f"(c[2]), "+f"(c[3])
        : "r"(a[0]), "r"(a[1]), "r"(a[2]), "r"(a[3]), "r"(b[0]), "r"(b[1]));
}
__device__ __forceinline__ void cp16(void* smem_dst, const void* gmem_src) {
    unsigned s = (unsigned)__cvta_generic_to_shared(smem_dst);
    asm volatile("cp.async.ca.shared.global [%0], [%1], 16;\n" :: "r"(s), "l"(gmem_src));
}
__device__ __forceinline__ unsigned enc_f(float f) {
    unsigned u = __float_as_uint(f);
    return (u & 0x80000000u) ? ~u : (u | 0x80000000u);
}
__device__ __forceinline__ float dec_f(unsigned e) {
    unsigned b = (e & 0x80000000u) ? (e ^ 0x80000000u) : ~e;
    return __uint_as_float(b);
}

// -------------------- prep: normalize vocab -> fp16 (padded) ----------------
__global__ void prep_vocab_kernel(const float* __restrict__ vocab) {
    int v = blockIdx.x;
    if (v >= CV) {
        for (int d = threadIdx.x; d < CD; d += 256)
            g_vn[(size_t)v * CD + d] = __float2half_rn(0.f);
        return;
    }
    __shared__ float red[256];
    float s = 0.f;
    for (int d = threadIdx.x; d < CD; d += 256) {
        float x = vocab[(size_t)v * CD + d];
        s += x * x;
    }
    red[threadIdx.x] = s; __syncthreads();
    for (int o = 128; o > 0; o >>= 1) {
        if (threadIdx.x < o) red[threadIdx.x] += red[threadIdx.x + o];
        __syncthreads();
    }
    float invn = 1.0f / sqrtf(red[0]);
    for (int d = threadIdx.x; d < CD; d += 256)
        g_vn[(size_t)v * CD + d] = __float2half_rn(vocab[(size_t)v * CD + d] * invn);
}

// -------------------- prep: convert conv weight to fp16 (K-major kept) ------
__global__ void conv_w_half_kernel(const float* __restrict__ W) {
    int i = blockIdx.x * 256 + threadIdx.x;
    if (i < CHD * CD) g_Wh[i] = __float2half_rn(W[i]);
}

// -------------------- init packed max --------------------------------------
__global__ void init_packed_kernel() {
    int i = blockIdx.x * 256 + threadIdx.x;
    if (i < CBN) g_packed[i] = 0ULL;
}

// -------------------- fused patch extraction + L2 norm ----------------------
__global__ void __launch_bounds__(256) extract_pnorm_kernel(const float* __restrict__ px) {
    int patch = blockIdx.x;               // 0..CBN-1
    int b = patch / CN, n = patch % CN;
    int hp = n / CG, wp = n % CG;
    const float* base = px + (size_t)b * CC * CHW * CHW;
    int tid = threadIdx.x, lane = tid & 31, w = tid >> 5;
    float ss = 0.f;
#pragma unroll
    for (int j = 0; j < 3; j++) {
        int d = tid + j * 256;
        int c = d >> 8, r = d & 255, ph = r >> 4, pw = r & 15;
        float x = base[((size_t)c * CHW + hp * CP + ph) * CHW + wp * CP + pw];
        g_patches[(size_t)patch * CD + d] = __float2half_rn(x);
        ss += x * x;
    }
#pragma unroll
    for (int o = 16; o > 0; o >>= 1) ss += __shfl_xor_sync(0xffffffffu, ss, o);
    __shared__ float ws[8];
    if (lane == 0) ws[w] = ss;
    __syncthreads();
    if (tid == 0) {
        float t = 0.f;
#pragma unroll
        for (int i = 0; i < 8; i++) t += ws[i];
        g_pnorm[patch] = sqrtf(t);
    }
}

// -------------------- fp16 GEMM config --------------------------------------
// BM=128 rows of A, BN=128 rows of B (= output cols), BK=32 (two k16 mma steps)
// A smem [128][40] halves (pad 40 -> conflict-free), B smem [128][40] halves.
#define BM 128
#define BN 128
#define BK 32
#define PAD_ST 40

// MODE 0: C = A@B^T + bias + pos   (emb)
// MODE 1: fused per-row max/argmax -> atomicMax g_packed (scores)
template <int MODE>
__global__ void __launch_bounds__(256, 2)
gemm_f16_kernel(const __half* __restrict__ A, const __half* __restrict__ Bg,
                float* __restrict__ C, const float* __restrict__ bias,
                const float* __restrict__ pos) {
    __shared__ __half As[2][BM][PAD_ST];
    __shared__ __half Bs[2][BN][PAD_ST];
    int tid = threadIdx.x, lane = tid & 31, warp = tid >> 5;
    int warpM = warp >> 2, warpN = warp & 3;
    int rowBase = blockIdx.y * BM, colBase = blockIdx.x * BN;
    int tig = lane & 3, grp = lane >> 2;

    float acc[4][4][4];
#pragma unroll
    for (int mi = 0; mi < 4; mi++)
#pragma unroll
        for (int ni = 0; ni < 4; ni++)
#pragma unroll
            for (int q = 0; q < 4; q++) acc[mi][ni][q] = 0.f;

    const int nk = CD / BK;  // 24

#define G_LOAD(ST, K0)                                                              \
    {                                                                               \
        _Pragma("unroll")                                                           \
        for (int i = 0; i < 2; i++) {                                               \
            int idx = tid + i * 256;                                                \
            int r = idx >> 2, c8 = (idx & 3) << 3;                                  \
            cp16(&As[ST][r][c8], &A[(size_t)(rowBase + r) * CD + (K0) + c8]);       \
        }                                                                           \
        _Pragma("unroll")                                                           \
        for (int i = 0; i < 2; i++) {                                               \
            int idx = tid + i * 256;                                                \
            int r = idx >> 2, c8 = (idx & 3) << 3;                                  \
            cp16(&Bs[ST][r][c8], &Bg[(size_t)(colBase + r) * CD + (K0) + c8]);      \
        }                                                                           \
        asm volatile("cp.async.commit_group;\n");                                   \
    }

    G_LOAD(0, 0);
    for (int kt = 0; kt < nk; kt++) {
        int st = kt & 1;
        if (kt + 1 < nk) {
            G_LOAD(st ^ 1, (kt + 1) * BK);
            asm volatile("cp.async.wait_group 1;\n");
        } else {
            asm volatile("cp.async.wait_group 0;\n");
        }
        __syncthreads();
#pragma unroll
        for (int kk = 0; kk < 2; kk++) {
            int kb = kk * 16;
            unsigned ua[4][4], ub[4][2];
#pragma unroll
            for (int mi = 0; mi < 4; mi++) {
                int m = warpM * 64 + mi * 16 + grp;
                ua[mi][0] = *reinterpret_cast<const unsigned*>(&As[st][m][kb + tig * 2]);
                ua[mi][1] = *reinterpret_cast<const unsigned*>(&As[st][m + 8][kb + tig * 2]);
                ua[mi][2] = *reinterpret_cast<const unsigned*>(&As[st][m][kb + 8 + tig * 2]);
                ua[mi][3] = *reinterpret_cast<const unsigned*>(&As[st][m + 8][kb + 8 + tig * 2]);
            }
#pragma unroll
            for (int ni = 0; ni < 4; ni++) {
                int nn = warpN * 32 + ni * 8 + grp;
                ub[ni][0] = *reinterpret_cast<const unsigned*>(&Bs[st][nn][kb + tig * 2]);
                ub[ni][1] = *reinterpret_cast<const unsigned*>(&Bs[st][nn][kb + 8 + tig * 2]);
            }
#pragma unroll
            for (int mi = 0; mi < 4; mi++)
#pragma unroll
                for (int ni = 0; ni < 4; ni++)
                    mma_f16(acc[mi][ni], ua[mi], ub[ni]);
        }
        __syncthreads();
    }
#undef G_LOAD

    if (MODE == 0) {
#pragma unroll
        for (int mi = 0; mi < 4; mi++) {
            int r0 = rowBase + warpM * 64 + mi * 16 + grp;
            int r1 = r0 + 8;
            int p0 = (r0 % CN) + 1, p1 = (r1 % CN) + 1;
#pragma unroll
            for (int ni = 0; ni < 4; ni++) {
                int col = colBase + warpN * 32 + ni * 8 + 2 * tig;
                float2 v0, v1;
                v0.x = acc[mi][ni][0] + bias[col]     + pos[(size_t)p0 * CHD + col];
                v0.y = acc[mi][ni][1] + bias[col + 1] + pos[(size_t)p0 * CHD + col + 1];
                v1.x = acc[mi][ni][2] + bias[col]     + pos[(size_t)p1 * CHD + col];
                v1.y = acc[mi][ni][3] + bias[col + 1] + pos[(size_t)p1 * CHD + col + 1];
                *reinterpret_cast<float2*>(&C[(size_t)r0 * CHD + col]) = v0;
                *reinterpret_cast<float2*>(&C[(size_t)r1 * CHD + col]) = v1;
            }
        }
    } else {
        // fused per-row max/argmax (ties -> smallest v)
#pragma unroll
        for (int mi = 0; mi < 4; mi++) {
#pragma unroll
            for (int h = 0; h < 2; h++) {
                int row = rowBase + warpM * 64 + mi * 16 + h * 8 + grp;
                unsigned long long p = 0ULL;
#pragma unroll
                for (int ni = 0; ni < 4; ni++) {
                    int col = colBase + warpN * 32 + ni * 8 + 2 * tig;
                    float s0 = acc[mi][ni][h * 2 + 0];
                    float s1 = acc[mi][ni][h * 2 + 1];
                    if (col < CV) {
                        unsigned long long q =
                            ((unsigned long long)enc_f(s0) << 32) | (0xFFFFFFFFu - (unsigned)col);
                        if (q > p) p = q;
                    }
                    if (col + 1 < CV) {
                        unsigned long long q =
                            ((unsigned long long)enc_f(s1) << 32) | (0xFFFFFFFFu - (unsigned)(col + 1));
                        if (q > p) p = q;
                    }
                }
                unsigned long long o;
                o = __shfl_xor_sync(0xffffffffu, p, 1); if (o > p) p = o;
                o = __shfl_xor_sync(0xffffffffu, p, 2); if (o > p) p = o;
                if (tig == 0 && p) atomicMax(&g_packed[row], p);
            }
        }
    }
}

// -------------------- mask + global scan -> raw labels ----------------------
__global__ void __launch_bounds__(1024) label_scan_kernel() {
    __shared__ int wsum[32];
    int tid = threadIdx.x, lane = tid & 31, w = tid >> 5;
    int running = 0;
    for (int base = 0; base < CBN; base += 1024) {
        int i = base + tid;
        unsigned long long p = g_packed[i];
        float score = dec_f((unsigned)(p >> 32));
        int v = (int)(0xFFFFFFFFu - (unsigned)(p & 0xFFFFFFFFu));
        float smin = 1.0f - score / g_pnorm[i];
        int m = (smin > 0.1f) ? 1 : 0;
        int x = m;
#pragma unroll
        for (int off = 1; off < 32; off <<= 1) {
            int y = __shfl_up_sync(0xffffffffu, x, off);
            if (lane >= off) x += y;
        }
        if (lane == 31) wsum[w] = x;
        __syncthreads();
        if (w == 0) {
            int s = wsum[lane];
#pragma unroll
            for (int off = 1; off < 32; off <<= 1) {
                int y = __shfl_up_sync(0xffffffffu, s, off);
                if (lane >= off) s += y;
            }
            wsum[lane] = s;
        }
        __syncthreads();
        int incl = x + ((w > 0) ? wsum[w - 1] : 0);
        int excl = incl - m;
        g_labels0[i] = m ? (CV + running + excl) : v;
        running += wsum[31];
        __syncthreads();
    }
}

// -------------------- per-row bitonic sort + unique-consecutive --------------
__global__ void __launch_bounds__(1024)
compact_kernel(float* __restrict__ labels_out) {
    __shared__ unsigned int key[1024];
    __shared__ int sc[1024];
    int b = blockIdx.x, tid = threadIdx.x;
    key[tid] = (tid < CN) ? ((((unsigned)g_labels0[b * CN + tid]) << 16) | (unsigned)tid)
                          : 0xFFFFFFFFu;
    __syncthreads();

    for (int k = 2; k <= 1024; k <<= 1) {
        for (int j = k >> 1; j > 0; j >>= 1) {
            int ixj = tid ^ j;
            if (ixj > tid) {
                unsigned a = key[tid], c2 = key[ixj];
                bool up = ((tid & k) == 0);
                if ((a > c2) == up) { key[tid] = c2; key[ixj] = a; }
            }
            __syncthreads();
        }
    }

    int lab     = (int)(key[tid] >> 16);
    int labprev = (tid > 0) ? (int)(key[tid - 1] >> 16) : -1;
    int step = (tid > 0 && tid < CN && lab != labprev) ? 1 : 0;
    sc[tid] = step; __syncthreads();
    for (int off = 1; off < 1024; off <<= 1) {
        int v = (tid >= off) ? sc[tid - off] : 0;
        __syncthreads();
        sc[tid] += v;
        __syncthreads();
    }
    if (tid < CN) {
        int l = sc[tid];
        int orig = (int)(key[tid] & 0xFFFFu);
        labels_out[(size_t)b * CN + orig] = (float)l;
        g_perm[b * CN + tid] = orig;
        if (tid == 0 || step) g_segstart[b * CNP1 + l] = tid;
    }
    __syncthreads();
    if (tid == 0) {
        int ns = sc[CN - 1] + 1;
        g_nseg[b] = ns;
        g_segstart[b * CNP1 + ns] = CN;
    }
}

// -------------------- segment means + cls + pad ------------------------------
__global__ void means_kernel(float* __restrict__ out, const float* __restrict__ cls,
                             const float* __restrict__ pos, const float* __restrict__ pad) {
    int b = blockIdx.y, r = blockIdx.x;
    float* o = out + ((size_t)b * CNP1 + r) * CHD;
    if (r == 0) {
        for (int h = threadIdx.x; h < CHD; h += blockDim.x)
            o[h] = cls[h] + pos[h];
        return;
    }
    int l = r - 1;
    if (l < g_nseg[b]) {
        int s0 = g_segstart[b * CNP1 + l];
        int s1 = g_segstart[b * CNP1 + l + 1];
        float cnt = (float)(s1 - s0);
        for (int h = threadIdx.x; h < CHD; h += blockDim.x) {
            float s = 0.f;
            for (int j = s0; j < s1; j++)
                s += g_emb[((size_t)b * CN + g_perm[b * CN + j]) * CHD + h];
            o[h] = s / cnt;
        }
    } else {
        for (int h = threadIdx.x; h < CHD; h += blockDim.x)
            o[h] = pad[h];
    }
}

// -------------------- attention mask -----------------------------------------
__global__ void attn_kernel(float* __restrict__ attn) {
    size_t idx = (size_t)blockIdx.x * blockDim.x + threadIdx.x;
    size_t total = (size_t)CB * CNP1 * CNP1;
    if (idx >= total) return;
    int j = (int)(idx % CNP1);
    int b = (int)(idx / ((size_t)CNP1 * CNP1));
    float v = 0.0f;
    if (j > 0 && (j - 1) >= g_nseg[b]) v = -3.4028234663852886e38f;  // -FLT_MAX
    attn[idx] = v;
}

// ---------------------------------------------------------------------------
extern "C" void kernel_launch(void* const* d_in, const int* in_sizes, int n_in,
                              void* d_out, int out_size) {
    (void)in_sizes; (void)n_in; (void)out_size;
    const float* px     = (const float*)d_in[0];
    const float* conv_w = (const float*)d_in[1];
    const float* conv_b = (const float*)d_in[2];
    const float* cls    = (const float*)d_in[3];
    const float* pos    = (const float*)d_in[4];
    const float* vocab  = (const float*)d_in[5];
    const float* pad    = (const float*)d_in[6];

    float* out        = (float*)d_out;
    float* labels_out = out + (size_t)CB * CNP1 * CHD;
    float* attn_out   = labels_out + (size_t)CB * CN;

    __half *patches, *Wh, *vn;
    float *emb;
    cudaGetSymbolAddress((void**)&patches, g_patches);
    cudaGetSymbolAddress((void**)&emb,     g_emb);
    cudaGetSymbolAddress((void**)&Wh,      g_Wh);
    cudaGetSymbolAddress((void**)&vn,      g_vn);

    init_packed_kernel<<<(CBN + 255) / 256, 256>>>();
    prep_vocab_kernel<<<CVP, 256>>>(vocab);
    conv_w_half_kernel<<<(CHD * CD + 255) / 256, 256>>>(conv_w);
    extract_pnorm_kernel<<<CBN, 256>>>(px);

    // emb: cols=768 -> 6 col tiles; scores: cols=1024 (padded) -> 8 col tiles
    gemm_f16_kernel<0><<<dim3(CHD / BN, CBN / BM), 256>>>(patches, Wh, emb, conv_b, pos);
    gemm_f16_kernel<1><<<dim3(CVP / BN, CBN / BM), 256>>>(patches, vn, nullptr, nullptr, nullptr);

    label_scan_kernel<<<1, 1024>>>();
    compact_kernel<<<CB, 1024>>>(labels_out);
    means_kernel<<<dim3(CNP1, CB), 256>>>(out, cls, pos, pad);

    {
        size_t total = (size_t)CB * CNP1 * CNP1;
        attn_kernel<<<(unsigned)((total + 255) / 256), 256>>>(attn_out);
    }
}

// round 9
// speedup vs baseline: 4.9978x; 1.0856x over previous
#include <cuda_runtime.h>
#include <cuda_fp16.h>
#include <math.h>
#include <stdint.h>

// ---------------------------------------------------------------------------
// InterImageTokenizer — fp16 m16n8k16 + ldmatrix round.
// Fixed shapes: B=64, C=3, HW=384, P=16 -> N=576, D=Hd=768, V=1000.
// ---------------------------------------------------------------------------

constexpr int CB   = 64;
constexpr int CC   = 3;
constexpr int CHW  = 384;
constexpr int CP   = 16;
constexpr int CG   = CHW / CP;      // 24
constexpr int CN   = CG * CG;       // 576
constexpr int CD   = CC * CP * CP;  // 768
constexpr int CHD  = 768;
constexpr int CV   = 1000;
constexpr int CVP  = 1024;          // padded vocab rows
constexpr int CBN  = CB * CN;       // 36864
constexpr int CNP1 = CN + 1;        // 577

// -------------------- device scratch ---------------------------------------
__device__ __half g_patches[(size_t)CBN * CD];    // fp16, [M][K]
__device__ float  g_emb[(size_t)CBN * CHD];
__device__ __half g_Wh[CHD * CD];                 // conv_w fp16, [h][d] K-major
__device__ __half g_vn[(size_t)CVP * CD];         // normalized vocab fp16, padded
__device__ float  g_pnorm[CBN];
__device__ unsigned long long g_packed[CBN];      // (ordered_score<<32)|(~v)
__device__ int   g_labels0[CBN];
__device__ int   g_perm[CB * CN];
__device__ int   g_segstart[CB * CNP1];
__device__ int   g_nseg[CB];

// -------------------- helpers ----------------------------------------------
__device__ __forceinline__ void mma_f16(float* c, const unsigned* a, const unsigned* b) {
    asm volatile(
        "mma.sync.aligned.m16n8k16.row.col.f32.f16.f16.f32 "
        "{%0,%1,%2,%3}, {%4,%5,%6,%7}, {%8,%9}, {%0,%1,%2,%3};"
        : "+f"(c[0]), "+f"(c[1]), "+f"(c[2]), "+f"(c[3])
        : "r"(a[0]), "r"(a[1]), "r"(a[2]), "r"(a[3]), "r"(b[0]), "r"(b[1]));
}
__device__ __forceinline__ void ldsm_x4(unsigned& r0, unsigned& r1, unsigned& r2,
                                        unsigned& r3, const void* p) {
    unsigned a = (unsigned)__cvta_generic_to_shared(p);
    asm volatile("ldmatrix.sync.aligned.m8n8.x4.shared.b16 {%0,%1,%2,%3}, [%4];"
                 : "=r"(r0), "=r"(r1), "=r"(r2), "=r"(r3) : "r"(a));
}
__device__ __forceinline__ void cp16(void* smem_dst, const void* gmem_src) {
    unsigned s = (unsigned)__cvta_generic_to_shared(smem_dst);
    asm volatile("cp.async.ca.shared.global [%0], [%1], 16;\n" :: "r"(s), "l"(gmem_src));
}
__device__ __forceinline__ unsigned enc_f(float f) {
    unsigned u = __float_as_uint(f);
    return (u & 0x80000000u) ? ~u : (u | 0x80000000u);
}
__device__ __forceinline__ float dec_f(unsigned e) {
    unsigned b = (e & 0x80000000u) ? (e ^ 0x80000000u) : ~e;
    return __uint_as_float(b);
}

// -------------------- prep: normalize vocab -> fp16 (padded) ----------------
__global__ void prep_vocab_kernel(const float* __restrict__ vocab) {
    int v = blockIdx.x;
    if (v >= CV) {
        for (int d = threadIdx.x; d < CD; d += 256)
            g_vn[(size_t)v * CD + d] = __float2half_rn(0.f);
        return;
    }
    __shared__ float red[256];
    float s = 0.f;
    for (int d = threadIdx.x; d < CD; d += 256) {
        float x = vocab[(size_t)v * CD + d];
        s += x * x;
    }
    red[threadIdx.x] = s; __syncthreads();
    for (int o = 128; o > 0; o >>= 1) {
        if (threadIdx.x < o) red[threadIdx.x] += red[threadIdx.x + o];
        __syncthreads();
    }
    float invn = 1.0f / sqrtf(red[0]);
    for (int d = threadIdx.x; d < CD; d += 256)
        g_vn[(size_t)v * CD + d] = __float2half_rn(vocab[(size_t)v * CD + d] * invn);
}

// -------------------- prep: convert conv weight to fp16 (K-major kept) ------
__global__ void conv_w_half_kernel(const float* __restrict__ W) {
    int i = blockIdx.x * 256 + threadIdx.x;
    if (i < CHD * CD) g_Wh[i] = __float2half_rn(W[i]);
}

// -------------------- init packed max --------------------------------------
__global__ void init_packed_kernel() {
    int i = blockIdx.x * 256 + threadIdx.x;
    if (i < CBN) g_packed[i] = 0ULL;
}

// -------------------- fused patch extraction + L2 norm (float4) -------------
__global__ void __launch_bounds__(192) extract_pnorm_kernel(const float* __restrict__ px) {
    int patch = blockIdx.x;               // 0..CBN-1
    int b = patch / CN, n = patch % CN;
    int hp = n / CG, wp = n % CG;
    const float* base = px + ((size_t)b * CC * CHW + (size_t)hp * CP) * CHW + wp * CP;
    int tid = threadIdx.x, lane = tid & 31, w = tid >> 5;
    // thread handles float4 at d4 = tid*4: c = d4>>8, r = d4&255, ph = r>>4, pw = r&15
    int d4 = tid << 2;
    int c = d4 >> 8, r = d4 & 255, ph = r >> 4, pw = r & 15;
    float4 x = *reinterpret_cast<const float4*>(
        &base[((size_t)c * CHW + ph) * CHW + pw]);
    __half2 h01 = __floats2half2_rn(x.x, x.y);
    __half2 h23 = __floats2half2_rn(x.z, x.w);
    *reinterpret_cast<uint2*>(&g_patches[(size_t)patch * CD + d4]) =
        make_uint2(*reinterpret_cast<unsigned*>(&h01), *reinterpret_cast<unsigned*>(&h23));
    float ss = x.x * x.x + x.y * x.y + x.z * x.z + x.w * x.w;
#pragma unroll
    for (int o = 16; o > 0; o >>= 1) ss += __shfl_xor_sync(0xffffffffu, ss, o);
    __shared__ float ws[6];
    if (lane == 0) ws[w] = ss;
    __syncthreads();
    if (tid == 0) {
        float t = ws[0] + ws[1] + ws[2] + ws[3] + ws[4] + ws[5];
        g_pnorm[patch] = sqrtf(t);
    }
}

// -------------------- fp16 GEMM config --------------------------------------
// BM=128 rows of A, BN=128 rows of B (= output cols), BK=32 (two k16 mma steps)
// A smem [128][40] halves (pad 40 -> conflict-free), B smem [128][40] halves.
#define BM 128
#define BN 128
#define BK 32
#define PAD_ST 40

// MODE 0: C = A@B^T + bias + pos   (emb)
// MODE 1: fused per-row max/argmax -> atomicMax g_packed (scores)
template <int MODE>
__global__ void __launch_bounds__(256, 2)
gemm_f16_kernel(const __half* __restrict__ A, const __half* __restrict__ Bg,
                float* __restrict__ C, const float* __restrict__ bias,
                const float* __restrict__ pos) {
    __shared__ __half As[2][BM][PAD_ST];
    __shared__ __half Bs[2][BN][PAD_ST];
    int tid = threadIdx.x, lane = tid & 31, warp = tid >> 5;
    int warpM = warp >> 2, warpN = warp & 3;
    int rowBase = blockIdx.y * BM, colBase = blockIdx.x * BN;
    int tig = lane & 3, grp = lane >> 2;
    int lrow = lane & 15, lhi = (lane >> 4) << 3;   // ldmatrix row / col-half

    float acc[4][4][4];
#pragma unroll
    for (int mi = 0; mi < 4; mi++)
#pragma unroll
        for (int ni = 0; ni < 4; ni++)
#pragma unroll
            for (int q = 0; q < 4; q++) acc[mi][ni][q] = 0.f;

    const int nk = CD / BK;  // 24

#define G_LOAD(ST, K0)                                                              \
    {                                                                               \
        _Pragma("unroll")                                                           \
        for (int i = 0; i < 2; i++) {                                               \
            int idx = tid + i * 256;                                                \
            int r = idx >> 2, c8 = (idx & 3) << 3;                                  \
            cp16(&As[ST][r][c8], &A[(size_t)(rowBase + r) * CD + (K0) + c8]);       \
        }                                                                           \
        _Pragma("unroll")                                                           \
        for (int i = 0; i < 2; i++) {                                               \
            int idx = tid + i * 256;                                                \
            int r = idx >> 2, c8 = (idx & 3) << 3;                                  \
            cp16(&Bs[ST][r][c8], &Bg[(size_t)(colBase + r) * CD + (K0) + c8]);      \
        }                                                                           \
        asm volatile("cp.async.commit_group;\n");                                   \
    }

    G_LOAD(0, 0);
    for (int kt = 0; kt < nk; kt++) {
        int st = kt & 1;
        if (kt + 1 < nk) {
            G_LOAD(st ^ 1, (kt + 1) * BK);
            asm volatile("cp.async.wait_group 1;\n");
        } else {
            asm volatile("cp.async.wait_group 0;\n");
        }
        __syncthreads();
#pragma unroll
        for (int kk = 0; kk < 2; kk++) {
            int kb = kk * 16;
            unsigned ua[4][4], ub[4][2];
#pragma unroll
            for (int mi = 0; mi < 4; mi++) {
                ldsm_x4(ua[mi][0], ua[mi][1], ua[mi][2], ua[mi][3],
                        &As[st][warpM * 64 + mi * 16 + lrow][kb + lhi]);
            }
#pragma unroll
            for (int p = 0; p < 2; p++) {
                ldsm_x4(ub[2 * p][0], ub[2 * p + 1][0], ub[2 * p][1], ub[2 * p + 1][1],
                        &Bs[st][warpN * 32 + p * 16 + lrow][kb + lhi]);
            }
#pragma unroll
            for (int mi = 0; mi < 4; mi++)
#pragma unroll
                for (int ni = 0; ni < 4; ni++)
                    mma_f16(acc[mi][ni], ua[mi], ub[ni]);
        }
        __syncthreads();
    }
#undef G_LOAD

    if (MODE == 0) {
#pragma unroll
        for (int mi = 0; mi < 4; mi++) {
            int r0 = rowBase + warpM * 64 + mi * 16 + grp;
            int r1 = r0 + 8;
            int p0 = (r0 % CN) + 1, p1 = (r1 % CN) + 1;
#pragma unroll
            for (int ni = 0; ni < 4; ni++) {
                int col = colBase + warpN * 32 + ni * 8 + 2 * tig;
                float2 v0, v1;
                v0.x = acc[mi][ni][0] + bias[col]     + pos[(size_t)p0 * CHD + col];
                v0.y = acc[mi][ni][1] + bias[col + 1] + pos[(size_t)p0 * CHD + col + 1];
                v1.x = acc[mi][ni][2] + bias[col]     + pos[(size_t)p1 * CHD + col];
                v1.y = acc[mi][ni][3] + bias[col + 1] + pos[(size_t)p1 * CHD + col + 1];
                *reinterpret_cast<float2*>(&C[(size_t)r0 * CHD + col]) = v0;
                *reinterpret_cast<float2*>(&C[(size_t)r1 * CHD + col]) = v1;
            }
        }
    } else {
        // fused per-row max/argmax (ties -> smallest v)
#pragma unroll
        for (int mi = 0; mi < 4; mi++) {
#pragma unroll
            for (int h = 0; h < 2; h++) {
                int row = rowBase + warpM * 64 + mi * 16 + h * 8 + grp;
                unsigned long long p = 0ULL;
#pragma unroll
                for (int ni = 0; ni < 4; ni++) {
                    int col = colBase + warpN * 32 + ni * 8 + 2 * tig;
                    float s0 = acc[mi][ni][h * 2 + 0];
                    float s1 = acc[mi][ni][h * 2 + 1];
                    if (col < CV) {
                        unsigned long long q =
                            ((unsigned long long)enc_f(s0) << 32) | (0xFFFFFFFFu - (unsigned)col);
                        if (q > p) p = q;
                    }
                    if (col + 1 < CV) {
                        unsigned long long q =
                            ((unsigned long long)enc_f(s1) << 32) | (0xFFFFFFFFu - (unsigned)(col + 1));
                        if (q > p) p = q;
                    }
                }
                unsigned long long o;
                o = __shfl_xor_sync(0xffffffffu, p, 1); if (o > p) p = o;
                o = __shfl_xor_sync(0xffffffffu, p, 2); if (o > p) p = o;
                if (tig == 0 && p) atomicMax(&g_packed[row], p);
            }
        }
    }
}

// -------------------- mask + global scan -> raw labels ----------------------
__global__ void __launch_bounds__(1024) label_scan_kernel() {
    __shared__ int wsum[32];
    int tid = threadIdx.x, lane = tid & 31, w = tid >> 5;
    int running = 0;
    for (int base = 0; base < CBN; base += 1024) {
        int i = base + tid;
        unsigned long long p = g_packed[i];
        float score = dec_f((unsigned)(p >> 32));
        int v = (int)(0xFFFFFFFFu - (unsigned)(p & 0xFFFFFFFFu));
        float smin = 1.0f - score / g_pnorm[i];
        int m = (smin > 0.1f) ? 1 : 0;
        int x = m;
#pragma unroll
        for (int off = 1; off < 32; off <<= 1) {
            int y = __shfl_up_sync(0xffffffffu, x, off);
            if (lane >= off) x += y;
        }
        if (lane == 31) wsum[w] = x;
        __syncthreads();
        if (w == 0) {
            int s = wsum[lane];
#pragma unroll
            for (int off = 1; off < 32; off <<= 1) {
                int y = __shfl_up_sync(0xffffffffu, s, off);
                if (lane >= off) s += y;
            }
            wsum[lane] = s;
        }
        __syncthreads();
        int incl = x + ((w > 0) ? wsum[w - 1] : 0);
        int excl = incl - m;
        g_labels0[i] = m ? (CV + running + excl) : v;
        running += wsum[31];
        __syncthreads();
    }
}

// -------------------- per-row bitonic sort + unique-consecutive --------------
__global__ void __launch_bounds__(1024)
compact_kernel(float* __restrict__ labels_out) {
    __shared__ unsigned int key[1024];
    __shared__ int sc[1024];
    int b = blockIdx.x, tid = threadIdx.x;
    key[tid] = (tid < CN) ? ((((unsigned)g_labels0[b * CN + tid]) << 16) | (unsigned)tid)
                          : 0xFFFFFFFFu;
    __syncthreads();

    for (int k = 2; k <= 1024; k <<= 1) {
        for (int j = k >> 1; j > 0; j >>= 1) {
            int ixj = tid ^ j;
            if (ixj > tid) {
                unsigned a = key[tid], c2 = key[ixj];
                bool up = ((tid & k) == 0);
                if ((a > c2) == up) { key[tid] = c2; key[ixj] = a; }
            }
            __syncthreads();
        }
    }

    int lab     = (int)(key[tid] >> 16);
    int labprev = (tid > 0) ? (int)(key[tid - 1] >> 16) : -1;
    int step = (tid > 0 && tid < CN && lab != labprev) ? 1 : 0;
    sc[tid] = step; __syncthreads();
    for (int off = 1; off < 1024; off <<= 1) {
        int v = (tid >= off) ? sc[tid - off] : 0;
        __syncthreads();
        sc[tid] += v;
        __syncthreads();
    }
    if (tid < CN) {
        int l = sc[tid];
        int orig = (int)(key[tid] & 0xFFFFu);
        labels_out[(size_t)b * CN + orig] = (float)l;
        g_perm[b * CN + tid] = orig;
        if (tid == 0 || step) g_segstart[b * CNP1 + l] = tid;
    }
    __syncthreads();
    if (tid == 0) {
        int ns = sc[CN - 1] + 1;
        g_nseg[b] = ns;
        g_segstart[b * CNP1 + ns] = CN;
    }
}

// -------------------- segment means + cls + pad ------------------------------
__global__ void means_kernel(float* __restrict__ out, const float* __restrict__ cls,
                             const float* __restrict__ pos, const float* __restrict__ pad) {
    int b = blockIdx.y, r = blockIdx.x;
    float* o = out + ((size_t)b * CNP1 + r) * CHD;
    if (r == 0) {
        for (int h = threadIdx.x; h < CHD; h += blockDim.x)
            o[h] = cls[h] + pos[h];
        return;
    }
    int l = r - 1;
    if (l < g_nseg[b]) {
        int s0 = g_segstart[b * CNP1 + l];
        int s1 = g_segstart[b * CNP1 + l + 1];
        float cnt = (float)(s1 - s0);
        for (int h = threadIdx.x; h < CHD; h += blockDim.x) {
            float s = 0.f;
            for (int j = s0; j < s1; j++)
                s += g_emb[((size_t)b * CN + g_perm[b * CN + j]) * CHD + h];
            o[h] = s / cnt;
        }
    } else {
        for (int h = threadIdx.x; h < CHD; h += blockDim.x)
            o[h] = pad[h];
    }
}

// -------------------- attention mask -----------------------------------------
__global__ void attn_kernel(float* __restrict__ attn) {
    size_t idx = (size_t)blockIdx.x * blockDim.x + threadIdx.x;
    size_t total = (size_t)CB * CNP1 * CNP1;
    if (idx >= total) return;
    int j = (int)(idx % CNP1);
    int b = (int)(idx / ((size_t)CNP1 * CNP1));
    float v = 0.0f;
    if (j > 0 && (j - 1) >= g_nseg[b]) v = -3.4028234663852886e38f;  // -FLT_MAX
    attn[idx] = v;
}

// ---------------------------------------------------------------------------
extern "C" void kernel_launch(void* const* d_in, const int* in_sizes, int n_in,
                              void* d_out, int out_size) {
    (void)in_sizes; (void)n_in; (void)out_size;
    const float* px     = (const float*)d_in[0];
    const float* conv_w = (const float*)d_in[1];
    const float* conv_b = (const float*)d_in[2];
    const float* cls    = (const float*)d_in[3];
    const float* pos    = (const float*)d_in[4];
    const float* vocab  = (const float*)d_in[5];
    const float* pad    = (const float*)d_in[6];

    float* out        = (float*)d_out;
    float* labels_out = out + (size_t)CB * CNP1 * CHD;
    float* attn_out   = labels_out + (size_t)CB * CN;

    __half *patches, *Wh, *vn;
    float *emb;
    cudaGetSymbolAddress((void**)&patches, g_patches);
    cudaGetSymbolAddress((void**)&emb,     g_emb);
    cudaGetSymbolAddress((void**)&Wh,      g_Wh);
    cudaGetSymbolAddress((void**)&vn,      g_vn);

    init_packed_kernel<<<(CBN + 255) / 256, 256>>>();
    prep_vocab_kernel<<<CVP, 256>>>(vocab);
    conv_w_half_kernel<<<(CHD * CD + 255) / 256, 256>>>(conv_w);
    extract_pnorm_kernel<<<CBN, 192>>>(px);

    // emb: cols=768 -> 6 col tiles; scores: cols=1024 (padded) -> 8 col tiles
    gemm_f16_kernel<0><<<dim3(CHD / BN, CBN / BM), 256>>>(patches, Wh, emb, conv_b, pos);
    gemm_f16_kernel<1><<<dim3(CVP / BN, CBN / BM), 256>>>(patches, vn, nullptr, nullptr, nullptr);

    label_scan_kernel<<<1, 1024>>>();
    compact_kernel<<<CB, 1024>>>(labels_out);
    means_kernel<<<dim3(CNP1, CB), 256>>>(out, cls, pos, pad);

    {
        size_t total = (size_t)CB * CNP1 * CNP1;
        attn_kernel<<<(unsigned)((total + 255) / 256), 256>>>(attn_out);
    }
}